// round 12
// baseline (speedup 1.0000x reference)
#include <cuda_runtime.h>
#include <cuda_bf16.h>
#include <math.h>
#include <stdint.h>

// Problem constants
#define NEXP 8
#define TOPK 2
#define DH   1024
#define FH   4096
#define NTOK 4096
#define NSLOT (NTOK * TOPK)   // 8192

// ---------------- scratch (static __device__ — no allocations) -------------
__device__ __nv_bfloat16 g_X_hi[(size_t)NTOK * DH];
__device__ __nv_bfloat16 g_X_lo[(size_t)NTOK * DH];
__device__ __nv_bfloat16 g_fcwT_hi[(size_t)NEXP * FH * DH];  // [e][n(F)][k(D)]
__device__ __nv_bfloat16 g_fcwT_lo[(size_t)NEXP * FH * DH];
__device__ __nv_bfloat16 g_prjT_hi[(size_t)NEXP * DH * FH];  // [e][n(D)][k(F)]
__device__ __nv_bfloat16 g_prjT_lo[(size_t)NEXP * DH * FH];
__device__ __nv_bfloat16 g_H_hi[(size_t)NSLOT * FH];
__device__ __nv_bfloat16 g_H_lo[(size_t)NSLOT * FH];
__device__ float g_O[(size_t)NSLOT * DH];
__device__ int   g_count[NEXP];     // statically zero; re-zeroed by combine
__device__ int   g_cursor[NEXP];
__device__ int   g_off[NEXP + 1];
__device__ int   g_eid[NSLOT];
__device__ float g_wk[NSLOT];
__device__ int   g_tok[NSLOT];
__device__ float g_wt[NSLOT];
__device__ int   g_slot[NSLOT];

// ---------------- generic-PTX helpers ---------------------------------------
__device__ __forceinline__ uint32_t smem_u32(const void* p) {
    uint32_t a;
    asm("{ .reg .u64 t; cvta.to.shared.u64 t, %1; cvt.u32.u64 %0, t; }" : "=r"(a) : "l"(p));
    return a;
}
__device__ __forceinline__ void cp16(uint32_t dst, const void* src, int srcsize) {
    asm volatile("cp.async.cg.shared.global [%0], [%1], 16, %2;"
                 :: "r"(dst), "l"(src), "r"(srcsize) : "memory");
}
#define CP_COMMIT() asm volatile("cp.async.commit_group;" ::: "memory")
#define CP_WAIT0()  asm volatile("cp.async.wait_group 0;" ::: "memory")

__device__ __forceinline__ void ldsm_x4(uint32_t* r, uint32_t addr) {
    asm volatile("ldmatrix.sync.aligned.m8n8.x4.shared.b16 {%0,%1,%2,%3}, [%4];"
                 : "=r"(r[0]), "=r"(r[1]), "=r"(r[2]), "=r"(r[3]) : "r"(addr));
}
__device__ __forceinline__ void mma16816(float* d, const uint32_t* a, uint32_t b0, uint32_t b1) {
    asm volatile(
        "mma.sync.aligned.m16n8k16.row.col.f32.bf16.bf16.f32 "
        "{%0,%1,%2,%3}, {%4,%5,%6,%7}, {%8,%9}, {%0,%1,%2,%3};"
        : "+f"(d[0]), "+f"(d[1]), "+f"(d[2]), "+f"(d[3])
        : "r"(a[0]), "r"(a[1]), "r"(a[2]), "r"(a[3]), "r"(b0), "r"(b1));
}

__device__ __forceinline__ float gelu_new(float v) {
    const float c = 0.7978845608028654f;
    float u = c * (v + 0.044715f * v * v * v);
    return 0.5f * v * (1.0f + tanhf(u));
}
__device__ __forceinline__ uint32_t pack2(__nv_bfloat16 a, __nv_bfloat16 b) {
    return (uint32_t)__bfloat16_as_ushort(a) | ((uint32_t)__bfloat16_as_ushort(b) << 16);
}
__device__ __forceinline__ void split4(float4 v, uint2& hv, uint2& lv) {
    __nv_bfloat16 h0 = __float2bfloat16(v.x), h1 = __float2bfloat16(v.y);
    __nv_bfloat16 h2 = __float2bfloat16(v.z), h3 = __float2bfloat16(v.w);
    hv.x = pack2(h0, h1); hv.y = pack2(h2, h3);
    lv.x = pack2(__float2bfloat16(v.x - __bfloat162float(h0)),
                 __float2bfloat16(v.y - __bfloat162float(h1)));
    lv.y = pack2(__float2bfloat16(v.z - __bfloat162float(h2)),
                 __float2bfloat16(v.w - __bfloat162float(h3)));
}

// SMEM tile geometry: 192x128 CTA tile, K-stage = 32, row = 80 B
#define SROW_B   80
#define TM       192
#define TN       128
#define OFF_AH   0
#define OFF_AL   15360              // 192 rows * 80
#define OFF_BH   30720
#define OFF_BL   40960              // B: 128 rows * 80 = 10240
#define STAGE_B  51200
#define NSTAGE   2
#define SMEM_G1  (NSTAGE * STAGE_B + 1024)   // 103424  -> 2 CTAs/SM
#define SMEM_G2  (NSTAGE * STAGE_B)          // 102400
#define BLOCK    256
#define MT       ((NSLOT + TM - 1) / TM)     // 43 m-tiles (covers worst skew)

// ---------------- kernel 1: router + gate logits + x hi/lo split ------------
__global__ void router_split_kernel(const float* __restrict__ x,
                                    const float* __restrict__ gate_w,
                                    float* __restrict__ out_logits) {
    int warp = (blockIdx.x * blockDim.x + threadIdx.x) >> 5;
    int lane = threadIdx.x & 31;
    if (warp >= NTOK) return;
    const float* xp = x + (size_t)warp * DH;
    float acc[NEXP];
#pragma unroll
    for (int e = 0; e < NEXP; e++) acc[e] = 0.0f;
#pragma unroll
    for (int i = 0; i < DH / 128; i++) {
        int d = i * 128 + lane * 4;
        float4 v = *(const float4*)(xp + d);
        uint2 hv, lv; split4(v, hv, lv);
        *(uint2*)(g_X_hi + (size_t)warp * DH + d) = hv;
        *(uint2*)(g_X_lo + (size_t)warp * DH + d) = lv;
        const float* gw = gate_w + (size_t)d * NEXP;
#pragma unroll
        for (int e = 0; e < NEXP; e++)
            acc[e] += v.x * gw[e] + v.y * gw[NEXP + e]
                    + v.z * gw[2 * NEXP + e] + v.w * gw[3 * NEXP + e];
    }
#pragma unroll
    for (int e = 0; e < NEXP; e++)
#pragma unroll
        for (int o = 16; o > 0; o >>= 1)
            acc[e] += __shfl_xor_sync(0xffffffffu, acc[e], o);
    if (lane == 0) {
        if (out_logits)
#pragma unroll
            for (int e = 0; e < NEXP; e++) out_logits[warp * NEXP + e] = acc[e];
        int e0 = 0;
#pragma unroll
        for (int e = 1; e < NEXP; e++) if (acc[e] > acc[e0]) e0 = e;
        int e1 = (e0 == 0) ? 1 : 0;
#pragma unroll
        for (int e = 0; e < NEXP; e++) if (e != e0 && acc[e] > acc[e1]) e1 = e;
        float dlt = expf(acc[e1] - acc[e0]);
        float w0 = 1.0f / (1.0f + dlt);
        float w1 = dlt / (1.0f + dlt);
        g_eid[warp * 2 + 0] = e0; g_eid[warp * 2 + 1] = e1;
        g_wk [warp * 2 + 0] = w0; g_wk [warp * 2 + 1] = w1;
        atomicAdd(&g_count[e0], 1);
        atomicAdd(&g_count[e1], 1);
    }
}

// ---------------- kernel 2: fused scan + scatter (single block) --------------
__global__ void scan_scatter_kernel() {
    if (threadIdx.x == 0) {
        int acc = 0; g_off[0] = 0;
#pragma unroll
        for (int e = 0; e < NEXP; e++) { acc += g_count[e]; g_off[e + 1] = acc; }
    }
    __syncthreads();
    for (int t = threadIdx.x; t < NTOK; t += blockDim.x) {
#pragma unroll
        for (int k = 0; k < TOPK; k++) {
            int e = g_eid[t * 2 + k];
            int pos = g_off[e] + atomicAdd(&g_cursor[e], 1);
            g_tok[pos] = t;
            g_wt[pos]  = g_wk[t * 2 + k];
            g_slot[t * 2 + k] = pos;
        }
    }
}

// ------------- weight transpose + bf16 hi/lo split (vectorized stores) -------
__global__ __launch_bounds__(256)
void transpose_split_kernel(const float* __restrict__ src,
                            __nv_bfloat16* __restrict__ dh,
                            __nv_bfloat16* __restrict__ dl,
                            int K, int N) {
    __shared__ float t[32][33];
    int e = blockIdx.z;
    src += (size_t)e * K * N;
    dh  += (size_t)e * K * N;
    dl  += (size_t)e * K * N;
    int n0 = blockIdx.x * 32, k0 = blockIdx.y * 32;
    int xx = threadIdx.x, yy = threadIdx.y;  // (32, 8)
    int tid = yy * 32 + xx;
#pragma unroll
    for (int r = 0; r < 4; r++) {
        int k = yy + r * 8;
        t[k][xx] = src[(size_t)(k0 + k) * N + n0 + xx];
    }
    __syncthreads();
#pragma unroll
    for (int it = 0; it < 2; it++) {
        int j = it * 256 + tid;
        int n = j >> 4, kp = j & 15;
        float v0 = t[2 * kp][n], v1 = t[2 * kp + 1][n];
        __nv_bfloat16 h0 = __float2bfloat16(v0), h1 = __float2bfloat16(v1);
        __nv_bfloat16 l0 = __float2bfloat16(v0 - __bfloat162float(h0));
        __nv_bfloat16 l1 = __float2bfloat16(v1 - __bfloat162float(h1));
        size_t o = (size_t)(n0 + n) * K + k0 + 2 * kp;
        *(uint32_t*)(dh + o) = pack2(h0, h1);
        *(uint32_t*)(dl + o) = pack2(l0, l1);
    }
}

// ---------------- warp-level 48x64 3-pass compute over one 32-wide stage ----
// Register-lean: A-hi frags for passes 1&2, then SAME regs reloaded with A-lo
// for pass 3 (B-hi re-ldsm'd). 2 k-quarters; each issues half next-stage loads.
struct WarpAcc { float a[3][8][4]; };   // [mi][nfrag][frag] = 96 floats

template <typename F>
__device__ __forceinline__ void compute_stage(uint32_t stb, int lane, int wm, int wn,
                                              WarpAcc& W, F&& issue_chunk) {
#pragma unroll
    for (int q = 0; q < 2; q++) {
        issue_chunk(q);                     // 5 cp16/thread for next stage
        int kk = q * 16;
        uint32_t af[3][4];
        uint32_t aoff = stb + OFF_AH
                      + (uint32_t)(wm + (lane & 15)) * SROW_B
                      + (uint32_t)(kk + ((lane >> 4) << 3)) * 2;
        int bgrp = lane >> 3;
        uint32_t boff = stb + OFF_BH
                      + (uint32_t)(wn + (lane & 7) + ((bgrp & 2) << 2)) * SROW_B
                      + (uint32_t)(kk + ((bgrp & 1) << 3)) * 2;
        // passes 1 & 2: A-hi x (B-hi, B-lo)
#pragma unroll
        for (int mi = 0; mi < 3; mi++) ldsm_x4(af[mi], aoff + mi * 16 * SROW_B);
#pragma unroll
        for (int p = 0; p < 4; p++) {
            uint32_t th[4], tl[4];
            ldsm_x4(th, boff + p * 16 * SROW_B);
            ldsm_x4(tl, boff + p * 16 * SROW_B + (OFF_BL - OFF_BH));
#pragma unroll
            for (int mi = 0; mi < 3; mi++) {
                mma16816(W.a[mi][2 * p],     af[mi], th[0], th[1]);
                mma16816(W.a[mi][2 * p + 1], af[mi], th[2], th[3]);
            }
#pragma unroll
            for (int mi = 0; mi < 3; mi++) {
                mma16816(W.a[mi][2 * p],     af[mi], tl[0], tl[1]);
                mma16816(W.a[mi][2 * p + 1], af[mi], tl[2], tl[3]);
            }
        }
        // pass 3: A-lo x B-hi (reuse af regs, re-ldsm B-hi)
#pragma unroll
        for (int mi = 0; mi < 3; mi++)
            ldsm_x4(af[mi], aoff + mi * 16 * SROW_B + (OFF_AL - OFF_AH));
#pragma unroll
        for (int p = 0; p < 4; p++) {
            uint32_t th[4];
            ldsm_x4(th, boff + p * 16 * SROW_B);
#pragma unroll
            for (int mi = 0; mi < 3; mi++) {
                mma16816(W.a[mi][2 * p],     af[mi], th[0], th[1]);
                mma16816(W.a[mi][2 * p + 1], af[mi], th[2], th[3]);
            }
        }
    }
}

// ---------------- GEMM1: H = gelu(x@fc_w + b), 192x128 tile, 2 CTA/SM -------
__global__ __launch_bounds__(BLOCK, 2)
void gemm1_mma(const float* __restrict__ fc_b) {
    int e = blockIdx.z;
    int row0 = g_off[e];
    int rows = g_off[e + 1] - row0;
    int m0 = blockIdx.x * TM;
    if (m0 >= rows) return;
    int n0 = blockIdx.y * TN;

    extern __shared__ char smem[];
    uint32_t sb = smem_u32(smem);
    int tid = threadIdx.x, wid = tid >> 5, lane = tid & 31;

    int* s_tok = (int*)(smem + NSTAGE * STAGE_B);
    if (tid < TM) s_tok[tid] = (m0 + tid < rows) ? g_tok[row0 + m0 + tid] : -1;
    __syncthreads();

    const __nv_bfloat16* Bh = g_fcwT_hi + (size_t)e * FH * DH + (size_t)n0 * DH;
    const __nv_bfloat16* Bl = g_fcwT_lo + (size_t)e * FH * DH + (size_t)n0 * DH;

    const int NC = DH / 32;   // 32 stages

    // quarter q of stage c: q0 = A-hi(3) + B-hi(2), q1 = A-lo + B-lo
    auto issue = [&](int c, int q) {
        uint32_t stb = sb + (c & 1) * STAGE_B;
        int kt = c * 32;
        uint32_t aoffb = stb + (q ? OFF_AL : OFF_AH);
        const __nv_bfloat16* abase = q ? g_X_lo : g_X_hi;
#pragma unroll
        for (int i = 0; i < 3; i++) {   // A: 192 rows x 4 chunks = 768 sites
            int u = tid + i * BLOCK;
            int row = u >> 2, ch = u & 3;
            int t = s_tok[row];
            cp16(aoffb + row * SROW_B + ch * 16,
                 abase + (size_t)(t < 0 ? 0 : t) * DH + kt + ch * 8, t < 0 ? 0 : 16);
        }
        uint32_t boffb = stb + (q ? OFF_BL : OFF_BH);
        const __nv_bfloat16* bbase = q ? Bl : Bh;
#pragma unroll
        for (int i = 0; i < 2; i++) {   // B: 128 rows x 4 chunks = 512 sites
            int u = tid + i * BLOCK;
            int row = u >> 2, ch = u & 3;
            cp16(boffb + row * SROW_B + ch * 16,
                 bbase + (size_t)row * DH + kt + ch * 8, 16);
        }
    };

    WarpAcc W;
#pragma unroll
    for (int mi = 0; mi < 3; mi++)
#pragma unroll
        for (int ni = 0; ni < 8; ni++)
#pragma unroll
            for (int r = 0; r < 4; r++) W.a[mi][ni][r] = 0.0f;

    int wm = (wid & 3) * 48, wn = (wid >> 2) * 64;

    issue(0, 0); issue(0, 1); CP_COMMIT();
    for (int c = 0; c < NC; c++) {
        CP_WAIT0();
        __syncthreads();
        bool more = (c + 1 < NC);
        compute_stage(sb + (c & 1) * STAGE_B, lane, wm, wn, W,
                      [&](int q) { if (more) issue(c + 1, q); });
        CP_COMMIT();
    }

    const float* bias = fc_b + (size_t)e * FH;
#pragma unroll
    for (int mi = 0; mi < 3; mi++) {
#pragma unroll
        for (int rh = 0; rh < 2; rh++) {
            int m = wm + mi * 16 + (lane >> 2) + rh * 8;
            if (m0 + m >= rows) continue;
            size_t slot = (size_t)row0 + m0 + m;
#pragma unroll
            for (int ni = 0; ni < 8; ni++) {
                int n = n0 + wn + ni * 8 + 2 * (lane & 3);
                float2 bb = *(const float2*)(bias + n);
                float v0 = gelu_new(W.a[mi][ni][2 * rh + 0] + bb.x);
                float v1 = gelu_new(W.a[mi][ni][2 * rh + 1] + bb.y);
                __nv_bfloat16 h0 = __float2bfloat16(v0), h1 = __float2bfloat16(v1);
                __nv_bfloat16 l0 = __float2bfloat16(v0 - __bfloat162float(h0));
                __nv_bfloat16 l1 = __float2bfloat16(v1 - __bfloat162float(h1));
                *(uint32_t*)(g_H_hi + slot * FH + n) = pack2(h0, h1);
                *(uint32_t*)(g_H_lo + slot * FH + n) = pack2(l0, l1);
            }
        }
    }
}

// ---------------- GEMM2: O = wt * (H@proj_w + b), 192x128 tile, 2 CTA/SM ----
__global__ __launch_bounds__(BLOCK, 2)
void gemm2_mma(const float* __restrict__ proj_b) {
    int e = blockIdx.z;
    int row0 = g_off[e];
    int rows = g_off[e + 1] - row0;
    int m0 = blockIdx.x * TM;
    if (m0 >= rows) return;
    int n0 = blockIdx.y * TN;

    extern __shared__ char smem[];
    uint32_t sb = smem_u32(smem);
    int tid = threadIdx.x, wid = tid >> 5, lane = tid & 31;

    const __nv_bfloat16* Bh = g_prjT_hi + (size_t)e * DH * FH + (size_t)n0 * FH;
    const __nv_bfloat16* Bl = g_prjT_lo + (size_t)e * DH * FH + (size_t)n0 * FH;

    const int NC = FH / 32;   // 128 stages

    auto issue = [&](int c, int q) {
        uint32_t stb = sb + (c & 1) * STAGE_B;
        int kt = c * 32;
        uint32_t aoffb = stb + (q ? OFF_AL : OFF_AH);
        const __nv_bfloat16* abase = q ? g_H_lo : g_H_hi;
#pragma unroll
        for (int i = 0; i < 3; i++) {
            int u = tid + i * BLOCK;
            int row = u >> 2, ch = u & 3;
            bool ok = (m0 + row) < rows;
            size_t slot = (size_t)row0 + m0 + (ok ? row : 0);
            cp16(aoffb + row * SROW_B + ch * 16,
                 abase + slot * FH + kt + ch * 8, ok ? 16 : 0);
        }
        uint32_t boffb = stb + (q ? OFF_BL : OFF_BH);
        const __nv_bfloat16* bbase = q ? Bl : Bh;
#pragma unroll
        for (int i = 0; i < 2; i++) {
            int u = tid + i * BLOCK;
            int row = u >> 2, ch = u & 3;
            cp16(boffb + row * SROW_B + ch * 16,
                 bbase + (size_t)row * FH + kt + ch * 8, 16);
        }
    };

    WarpAcc W;
#pragma unroll
    for (int mi = 0; mi < 3; mi++)
#pragma unroll
        for (int ni = 0; ni < 8; ni++)
#pragma unroll
            for (int r = 0; r < 4; r++) W.a[mi][ni][r] = 0.0f;

    int wm = (wid & 3) * 48, wn = (wid >> 2) * 64;

    issue(0, 0); issue(0, 1); CP_COMMIT();
    for (int c = 0; c < NC; c++) {
        CP_WAIT0();
        __syncthreads();
        bool more = (c + 1 < NC);
        compute_stage(sb + (c & 1) * STAGE_B, lane, wm, wn, W,
                      [&](int q) { if (more) issue(c + 1, q); });
        CP_COMMIT();
    }

    const float* bias = proj_b + (size_t)e * DH;
#pragma unroll
    for (int mi = 0; mi < 3; mi++) {
#pragma unroll
        for (int rh = 0; rh < 2; rh++) {
            int m = wm + mi * 16 + (lane >> 2) + rh * 8;
            if (m0 + m >= rows) continue;
            size_t slot = (size_t)row0 + m0 + m;
            float w = g_wt[slot];
#pragma unroll
            for (int ni = 0; ni < 8; ni++) {
                int n = n0 + wn + ni * 8 + 2 * (lane & 3);
                float2 bb = *(const float2*)(bias + n);
                float v0 = w * (W.a[mi][ni][2 * rh + 0] + bb.x);
                float v1 = w * (W.a[mi][ni][2 * rh + 1] + bb.y);
                *(float2*)(g_O + slot * DH + n) = make_float2(v0, v1);
            }
        }
    }
}

// ---------------- combine (+ counter reset for next call) --------------------
__global__ void combine_kernel(float* __restrict__ out) {
    if (blockIdx.x == 0 && threadIdx.x < NEXP) {
        g_count[threadIdx.x] = 0;
        g_cursor[threadIdx.x] = 0;
    }
    int idx = blockIdx.x * blockDim.x + threadIdx.x;
    const int DQ = DH / 4;
    if (idx >= NTOK * DQ) return;
    int t = idx / DQ;
    int dq = idx - t * DQ;
    int s0 = g_slot[t * 2 + 0];
    int s1 = g_slot[t * 2 + 1];
    const float4* o0 = (const float4*)(g_O + (size_t)s0 * DH) + dq;
    const float4* o1 = (const float4*)(g_O + (size_t)s1 * DH) + dq;
    float4 a = *o0, b = *o1;
    ((float4*)(out + (size_t)t * DH))[dq] =
        make_float4(a.x + b.x, a.y + b.y, a.z + b.z, a.w + b.w);
}

// ---------------- launch -----------------------------------------------------
extern "C" void kernel_launch(void* const* d_in, const int* in_sizes, int n_in,
                              void* d_out, int out_size) {
    const float* x      = (const float*)d_in[0];
    const float* gate_w = (const float*)d_in[1];
    const float* fc_w   = (const float*)d_in[2];
    const float* fc_b   = (const float*)d_in[3];
    const float* proj_w = (const float*)d_in[4];
    const float* proj_b = (const float*)d_in[5];

    float* out = (float*)d_out;
    float* out_logits =
        (out_size >= NTOK * DH + NTOK * NEXP) ? (out + (size_t)NTOK * DH) : nullptr;

    cudaFuncSetAttribute(gemm1_mma, cudaFuncAttributeMaxDynamicSharedMemorySize, SMEM_G1);
    cudaFuncSetAttribute(gemm2_mma, cudaFuncAttributeMaxDynamicSharedMemorySize, SMEM_G2);

    __nv_bfloat16 *fh, *fl, *ph, *pl;
    cudaGetSymbolAddress((void**)&fh, g_fcwT_hi);
    cudaGetSymbolAddress((void**)&fl, g_fcwT_lo);
    cudaGetSymbolAddress((void**)&ph, g_prjT_hi);
    cudaGetSymbolAddress((void**)&pl, g_prjT_lo);

    // ncu profiles the 4th launch -> keep it gemm1.
    router_split_kernel<<<NTOK / 8, 256>>>(x, gate_w, out_logits);                 // 1
    scan_scatter_kernel<<<1, 1024>>>();                                            // 2
    transpose_split_kernel<<<dim3(FH / 32, DH / 32, NEXP), dim3(32, 8)>>>(fc_w, fh, fl, DH, FH);   // 3
    gemm1_mma<<<dim3(MT, FH / TN, NEXP), BLOCK, SMEM_G1>>>(fc_b);                  // 4  <- profiled
    transpose_split_kernel<<<dim3(DH / 32, FH / 32, NEXP), dim3(32, 8)>>>(proj_w, ph, pl, FH, DH); // 5
    gemm2_mma<<<dim3(MT, DH / TN, NEXP), BLOCK, SMEM_G2>>>(proj_b);                // 6
    combine_kernel<<<(NTOK * (DH / 4) + 255) / 256, 256>>>(out);                   // 7

    (void)n_in; (void)in_sizes;
}

// round 13
// speedup vs baseline: 1.4333x; 1.4333x over previous
#include <cuda_runtime.h>
#include <cuda_bf16.h>
#include <math.h>
#include <stdint.h>

// Problem constants
#define NEXP 8
#define TOPK 2
#define DH   1024
#define FH   4096
#define NTOK 4096
#define NSLOT (NTOK * TOPK)   // 8192

// ---------------- scratch (static __device__ — no allocations) -------------
__device__ __nv_bfloat16 g_X_hi[(size_t)NTOK * DH];
__device__ __nv_bfloat16 g_X_lo[(size_t)NTOK * DH];
__device__ __nv_bfloat16 g_fcwT_hi[(size_t)NEXP * FH * DH];  // [e][n(F)][k(D)]
__device__ __nv_bfloat16 g_fcwT_lo[(size_t)NEXP * FH * DH];
__device__ __nv_bfloat16 g_prjT_hi[(size_t)NEXP * DH * FH];  // [e][n(D)][k(F)]
__device__ __nv_bfloat16 g_prjT_lo[(size_t)NEXP * DH * FH];
__device__ __nv_bfloat16 g_H_hi[(size_t)NSLOT * FH];
__device__ __nv_bfloat16 g_H_lo[(size_t)NSLOT * FH];
__device__ float g_O[(size_t)NSLOT * DH];
__device__ int   g_count[NEXP];     // statically zero; re-zeroed by combine
__device__ int   g_cursor[NEXP];
__device__ int   g_off[NEXP + 1];
__device__ int   g_mtpfx[NEXP + 1]; // per-expert m-tile prefix (128-row tiles)
__device__ int   g_eid[NSLOT];
__device__ float g_wk[NSLOT];
__device__ int   g_tok[NSLOT];
__device__ float g_wt[NSLOT];
__device__ int   g_slot[NSLOT];

// ---------------- generic-PTX helpers ---------------------------------------
__device__ __forceinline__ uint32_t smem_u32(const void* p) {
    uint32_t a;
    asm("{ .reg .u64 t; cvta.to.shared.u64 t, %1; cvt.u32.u64 %0, t; }" : "=r"(a) : "l"(p));
    return a;
}
__device__ __forceinline__ void cp16(uint32_t dst, const void* src, int srcsize) {
    asm volatile("cp.async.cg.shared.global [%0], [%1], 16, %2;"
                 :: "r"(dst), "l"(src), "r"(srcsize) : "memory");
}
#define CP_COMMIT() asm volatile("cp.async.commit_group;" ::: "memory")
#define CP_WAIT0()  asm volatile("cp.async.wait_group 0;" ::: "memory")

__device__ __forceinline__ void ldsm_x4(uint32_t* r, uint32_t addr) {
    asm volatile("ldmatrix.sync.aligned.m8n8.x4.shared.b16 {%0,%1,%2,%3}, [%4];"
                 : "=r"(r[0]), "=r"(r[1]), "=r"(r[2]), "=r"(r[3]) : "r"(addr));
}
__device__ __forceinline__ void mma16816(float* d, const uint32_t* a, uint32_t b0, uint32_t b1) {
    asm volatile(
        "mma.sync.aligned.m16n8k16.row.col.f32.bf16.bf16.f32 "
        "{%0,%1,%2,%3}, {%4,%5,%6,%7}, {%8,%9}, {%0,%1,%2,%3};"
        : "+f"(d[0]), "+f"(d[1]), "+f"(d[2]), "+f"(d[3])
        : "r"(a[0]), "r"(a[1]), "r"(a[2]), "r"(a[3]), "r"(b0), "r"(b1));
}

__device__ __forceinline__ float gelu_new(float v) {
    const float c = 0.7978845608028654f;
    float u = c * (v + 0.044715f * v * v * v);
    return 0.5f * v * (1.0f + tanhf(u));
}
__device__ __forceinline__ uint32_t pack2(__nv_bfloat16 a, __nv_bfloat16 b) {
    return (uint32_t)__bfloat16_as_ushort(a) | ((uint32_t)__bfloat16_as_ushort(b) << 16);
}
__device__ __forceinline__ void split4(float4 v, uint2& hv, uint2& lv) {
    __nv_bfloat16 h0 = __float2bfloat16(v.x), h1 = __float2bfloat16(v.y);
    __nv_bfloat16 h2 = __float2bfloat16(v.z), h3 = __float2bfloat16(v.w);
    hv.x = pack2(h0, h1); hv.y = pack2(h2, h3);
    lv.x = pack2(__float2bfloat16(v.x - __bfloat162float(h0)),
                 __float2bfloat16(v.y - __bfloat162float(h1)));
    lv.y = pack2(__float2bfloat16(v.z - __bfloat162float(h2)),
                 __float2bfloat16(v.w - __bfloat162float(h3)));
}

// SMEM tile geometry: 128x128 CTA tile, K-stage = 32, row = 80 B
#define SROW_B   80
#define OFF_AH   0
#define OFF_AL   10240              // 128 rows * 80
#define OFF_BH   20480
#define OFF_BL   30720
#define STAGE_B  40960
#define NSTAGE   2
#define SMEM_G1  (NSTAGE * STAGE_B + 512)   // 82432  -> 2 CTAs/SM
#define SMEM_G2  (NSTAGE * STAGE_B)
#define BLOCK    256
#define PGRID    296                // persistent grid: 2 CTAs x 148 SMs

// ---------------- kernel 1: router + gate logits + x hi/lo split ------------
__global__ void router_split_kernel(const float* __restrict__ x,
                                    const float* __restrict__ gate_w,
                                    float* __restrict__ out_logits) {
    int warp = (blockIdx.x * blockDim.x + threadIdx.x) >> 5;
    int lane = threadIdx.x & 31;
    if (warp >= NTOK) return;
    const float* xp = x + (size_t)warp * DH;
    float acc[NEXP];
#pragma unroll
    for (int e = 0; e < NEXP; e++) acc[e] = 0.0f;
#pragma unroll
    for (int i = 0; i < DH / 128; i++) {
        int d = i * 128 + lane * 4;
        float4 v = *(const float4*)(xp + d);
        uint2 hv, lv; split4(v, hv, lv);
        *(uint2*)(g_X_hi + (size_t)warp * DH + d) = hv;
        *(uint2*)(g_X_lo + (size_t)warp * DH + d) = lv;
        const float* gw = gate_w + (size_t)d * NEXP;
#pragma unroll
        for (int e = 0; e < NEXP; e++)
            acc[e] += v.x * gw[e] + v.y * gw[NEXP + e]
                    + v.z * gw[2 * NEXP + e] + v.w * gw[3 * NEXP + e];
    }
#pragma unroll
    for (int e = 0; e < NEXP; e++)
#pragma unroll
        for (int o = 16; o > 0; o >>= 1)
            acc[e] += __shfl_xor_sync(0xffffffffu, acc[e], o);
    if (lane == 0) {
        if (out_logits)
#pragma unroll
            for (int e = 0; e < NEXP; e++) out_logits[warp * NEXP + e] = acc[e];
        int e0 = 0;
#pragma unroll
        for (int e = 1; e < NEXP; e++) if (acc[e] > acc[e0]) e0 = e;
        int e1 = (e0 == 0) ? 1 : 0;
#pragma unroll
        for (int e = 0; e < NEXP; e++) if (e != e0 && acc[e] > acc[e1]) e1 = e;
        float dlt = expf(acc[e1] - acc[e0]);
        float w0 = 1.0f / (1.0f + dlt);
        float w1 = dlt / (1.0f + dlt);
        g_eid[warp * 2 + 0] = e0; g_eid[warp * 2 + 1] = e1;
        g_wk [warp * 2 + 0] = w0; g_wk [warp * 2 + 1] = w1;
        atomicAdd(&g_count[e0], 1);
        atomicAdd(&g_count[e1], 1);
    }
}

// ---------------- kernel 2: fused scan + scatter (single block) --------------
__global__ void scan_scatter_kernel() {
    if (threadIdx.x == 0) {
        int acc = 0, mt = 0;
        g_off[0] = 0; g_mtpfx[0] = 0;
#pragma unroll
        for (int e = 0; e < NEXP; e++) {
            acc += g_count[e]; g_off[e + 1] = acc;
            mt += (g_count[e] + 127) >> 7; g_mtpfx[e + 1] = mt;
        }
    }
    __syncthreads();
    for (int t = threadIdx.x; t < NTOK; t += blockDim.x) {
#pragma unroll
        for (int k = 0; k < TOPK; k++) {
            int e = g_eid[t * 2 + k];
            int pos = g_off[e] + atomicAdd(&g_cursor[e], 1);
            g_tok[pos] = t;
            g_wt[pos]  = g_wk[t * 2 + k];
            g_slot[t * 2 + k] = pos;
        }
    }
}

// ------------- weight transpose + bf16 hi/lo split (vectorized stores) -------
__global__ __launch_bounds__(256)
void transpose_split_kernel(const float* __restrict__ src,
                            __nv_bfloat16* __restrict__ dh,
                            __nv_bfloat16* __restrict__ dl,
                            int K, int N) {
    __shared__ float t[32][33];
    int e = blockIdx.z;
    src += (size_t)e * K * N;
    dh  += (size_t)e * K * N;
    dl  += (size_t)e * K * N;
    int n0 = blockIdx.x * 32, k0 = blockIdx.y * 32;
    int xx = threadIdx.x, yy = threadIdx.y;  // (32, 8)
    int tid = yy * 32 + xx;
#pragma unroll
    for (int r = 0; r < 4; r++) {
        int k = yy + r * 8;
        t[k][xx] = src[(size_t)(k0 + k) * N + n0 + xx];
    }
    __syncthreads();
#pragma unroll
    for (int it = 0; it < 2; it++) {
        int j = it * 256 + tid;
        int n = j >> 4, kp = j & 15;
        float v0 = t[2 * kp][n], v1 = t[2 * kp + 1][n];
        __nv_bfloat16 h0 = __float2bfloat16(v0), h1 = __float2bfloat16(v1);
        __nv_bfloat16 l0 = __float2bfloat16(v0 - __bfloat162float(h0));
        __nv_bfloat16 l1 = __float2bfloat16(v1 - __bfloat162float(h1));
        size_t o = (size_t)(n0 + n) * K + k0 + 2 * kp;
        *(uint32_t*)(dh + o) = pack2(h0, h1);
        *(uint32_t*)(dl + o) = pack2(l0, l1);
    }
}

// ---------------- warp-level 64x32 3-pass compute over one 32-wide stage ----
struct WarpAcc { float a[4][4][4]; };   // [mi][nfrag][frag]

template <typename F>
__device__ __forceinline__ void compute_stage(uint32_t stb, int lane, int wm, int wn,
                                              WarpAcc& W, F&& issue_chunk) {
#pragma unroll
    for (int q = 0; q < 2; q++) {
        issue_chunk(q);                     // 4 cp16/thread for next stage
        int kk = q * 16;
        uint32_t ah[4][4], al[4][4];
        uint32_t aoff = stb + OFF_AH
                      + (uint32_t)(wm + (lane & 15)) * SROW_B
                      + (uint32_t)(kk + ((lane >> 4) << 3)) * 2;
#pragma unroll
        for (int mi = 0; mi < 4; mi++) {
            ldsm_x4(ah[mi], aoff + mi * 16 * SROW_B);
            ldsm_x4(al[mi], aoff + mi * 16 * SROW_B + (OFF_AL - OFF_AH));
        }
        int bgrp = lane >> 3;
        uint32_t boff = stb + OFF_BH
                      + (uint32_t)(wn + (lane & 7) + ((bgrp & 2) << 2)) * SROW_B
                      + (uint32_t)(kk + ((bgrp & 1) << 3)) * 2;
#pragma unroll
        for (int p = 0; p < 2; p++) {           // n-frag pair (2p, 2p+1)
            uint32_t th[4], tl[4];
            ldsm_x4(th, boff + p * 16 * SROW_B);
            ldsm_x4(tl, boff + p * 16 * SROW_B + (OFF_BL - OFF_BH));
#pragma unroll
            for (int mi = 0; mi < 4; mi++) {
                mma16816(W.a[mi][2 * p],     ah[mi], th[0], th[1]);
                mma16816(W.a[mi][2 * p + 1], ah[mi], th[2], th[3]);
            }
#pragma unroll
            for (int mi = 0; mi < 4; mi++) {
                mma16816(W.a[mi][2 * p],     ah[mi], tl[0], tl[1]);
                mma16816(W.a[mi][2 * p + 1], ah[mi], tl[2], tl[3]);
            }
#pragma unroll
            for (int mi = 0; mi < 4; mi++) {
                mma16816(W.a[mi][2 * p],     al[mi], th[0], th[1]);
                mma16816(W.a[mi][2 * p + 1], al[mi], th[2], th[3]);
            }
        }
    }
}

// ---------------- GEMM1: persistent, 128x128 tile, 2 CTA/SM -----------------
__global__ __launch_bounds__(BLOCK, 2)
void gemm1_mma(const float* __restrict__ fc_b) {
    extern __shared__ char smem[];
    uint32_t sb = smem_u32(smem);
    int tid = threadIdx.x, wid = tid >> 5, lane = tid & 31;
    int* s_tok = (int*)(smem + NSTAGE * STAGE_B);
    int wm = (wid & 1) * 64, wn = (wid >> 1) * 32;
    const int NTL = FH / 128;   // 32 n-tiles
    int total_mt = g_mtpfx[NEXP];
    int total = total_mt * NTL;

    for (int tidx = blockIdx.x; tidx < total; tidx += gridDim.x) {
        int mtg = tidx % total_mt;
        int ni  = tidx / total_mt;
        int e = 0;
#pragma unroll
        for (int k = 0; k < NEXP - 1; k++) if (g_mtpfx[k + 1] <= mtg) e = k + 1;
        int row0 = g_off[e];
        int rows = g_off[e + 1] - row0;
        int m0 = (mtg - g_mtpfx[e]) * 128;
        int n0 = ni * 128;

        __syncthreads();   // previous tile fully done with smem
        if (tid < 128) s_tok[tid] = (m0 + tid < rows) ? g_tok[row0 + m0 + tid] : -1;
        __syncthreads();

        const __nv_bfloat16* Bh = g_fcwT_hi + (size_t)e * FH * DH + (size_t)n0 * DH;
        const __nv_bfloat16* Bl = g_fcwT_lo + (size_t)e * FH * DH + (size_t)n0 * DH;
        const int NC = DH / 32;   // 32 stages

        auto issue = [&](int c, int q) {
            uint32_t stb = sb + (c & 1) * STAGE_B;
            int kt = c * 32;
            if (q == 0) {
#pragma unroll
                for (int i = 0; i < 4; i++) {   // A: 2 slabs x 512 sites
                    int u = tid + (i & 1) * BLOCK;
                    int row = u >> 2, ch = u & 3;
                    int which = i >> 1;   // 0 hi, 1 lo
                    uint32_t dst = stb + (which ? OFF_AL : OFF_AH) + row * SROW_B + ch * 16;
                    int t = s_tok[row];
                    const __nv_bfloat16* base = which ? g_X_lo : g_X_hi;
                    cp16(dst, base + (size_t)(t < 0 ? 0 : t) * DH + kt + ch * 8, t < 0 ? 0 : 16);
                }
            } else {
#pragma unroll
                for (int i = 0; i < 4; i++) {   // B: 2 slabs x 512 sites
                    int u = tid + (i & 1) * BLOCK;
                    int row = u >> 2, ch = u & 3;
                    int which = i >> 1;
                    uint32_t dst = stb + (which ? OFF_BL : OFF_BH) + row * SROW_B + ch * 16;
                    const __nv_bfloat16* base = which ? Bl : Bh;
                    cp16(dst, base + (size_t)row * DH + kt + ch * 8, 16);
                }
            }
        };

        WarpAcc W;
#pragma unroll
        for (int mi = 0; mi < 4; mi++)
#pragma unroll
            for (int nf = 0; nf < 4; nf++)
#pragma unroll
                for (int r = 0; r < 4; r++) W.a[mi][nf][r] = 0.0f;

        issue(0, 0); issue(0, 1); CP_COMMIT();
        for (int c = 0; c < NC; c++) {
            CP_WAIT0();
            __syncthreads();
            bool more = (c + 1 < NC);
            compute_stage(sb + (c & 1) * STAGE_B, lane, wm, wn, W,
                          [&](int q) { if (more) issue(c + 1, q); });
            CP_COMMIT();
        }

        const float* bias = fc_b + (size_t)e * FH;
#pragma unroll
        for (int mi = 0; mi < 4; mi++) {
#pragma unroll
            for (int rh = 0; rh < 2; rh++) {
                int m = wm + mi * 16 + (lane >> 2) + rh * 8;
                if (m0 + m >= rows) continue;
                size_t slot = (size_t)row0 + m0 + m;
#pragma unroll
                for (int nf = 0; nf < 4; nf++) {
                    int n = n0 + wn + nf * 8 + 2 * (lane & 3);
                    float2 bb = *(const float2*)(bias + n);
                    float v0 = gelu_new(W.a[mi][nf][2 * rh + 0] + bb.x);
                    float v1 = gelu_new(W.a[mi][nf][2 * rh + 1] + bb.y);
                    __nv_bfloat16 h0 = __float2bfloat16(v0), h1 = __float2bfloat16(v1);
                    __nv_bfloat16 l0 = __float2bfloat16(v0 - __bfloat162float(h0));
                    __nv_bfloat16 l1 = __float2bfloat16(v1 - __bfloat162float(h1));
                    *(uint32_t*)(g_H_hi + slot * FH + n) = pack2(h0, h1);
                    *(uint32_t*)(g_H_lo + slot * FH + n) = pack2(l0, l1);
                }
            }
        }
    }
}

// ---------------- GEMM2: persistent, 128x128 tile, 2 CTA/SM -----------------
__global__ __launch_bounds__(BLOCK, 2)
void gemm2_mma(const float* __restrict__ proj_b) {
    extern __shared__ char smem[];
    uint32_t sb = smem_u32(smem);
    int tid = threadIdx.x, wid = tid >> 5, lane = tid & 31;
    int wm = (wid & 1) * 64, wn = (wid >> 1) * 32;
    const int NTL = DH / 128;   // 8 n-tiles
    int total_mt = g_mtpfx[NEXP];
    int total = total_mt * NTL;

    for (int tidx = blockIdx.x; tidx < total; tidx += gridDim.x) {
        int mtg = tidx % total_mt;
        int ni  = tidx / total_mt;
        int e = 0;
#pragma unroll
        for (int k = 0; k < NEXP - 1; k++) if (g_mtpfx[k + 1] <= mtg) e = k + 1;
        int row0 = g_off[e];
        int rows = g_off[e + 1] - row0;
        int m0 = (mtg - g_mtpfx[e]) * 128;
        int n0 = ni * 128;

        __syncthreads();

        const __nv_bfloat16* Bh = g_prjT_hi + (size_t)e * DH * FH + (size_t)n0 * FH;
        const __nv_bfloat16* Bl = g_prjT_lo + (size_t)e * DH * FH + (size_t)n0 * FH;
        const int NC = FH / 32;   // 128 stages

        auto issue = [&](int c, int q) {
            uint32_t stb = sb + (c & 1) * STAGE_B;
            int kt = c * 32;
            if (q == 0) {
#pragma unroll
                for (int i = 0; i < 4; i++) {
                    int u = tid + (i & 1) * BLOCK;
                    int row = u >> 2, ch = u & 3;
                    int which = i >> 1;
                    uint32_t dst = stb + (which ? OFF_AL : OFF_AH) + row * SROW_B + ch * 16;
                    bool ok = (m0 + row) < rows;
                    size_t slot = (size_t)row0 + m0 + (ok ? row : 0);
                    const __nv_bfloat16* base = which ? g_H_lo : g_H_hi;
                    cp16(dst, base + slot * FH + kt + ch * 8, ok ? 16 : 0);
                }
            } else {
#pragma unroll
                for (int i = 0; i < 4; i++) {
                    int u = tid + (i & 1) * BLOCK;
                    int row = u >> 2, ch = u & 3;
                    int which = i >> 1;
                    uint32_t dst = stb + (which ? OFF_BL : OFF_BH) + row * SROW_B + ch * 16;
                    const __nv_bfloat16* base = which ? Bl : Bh;
                    cp16(dst, base + (size_t)row * FH + kt + ch * 8, 16);
                }
            }
        };

        WarpAcc W;
#pragma unroll
        for (int mi = 0; mi < 4; mi++)
#pragma unroll
            for (int nf = 0; nf < 4; nf++)
#pragma unroll
                for (int r = 0; r < 4; r++) W.a[mi][nf][r] = 0.0f;

        issue(0, 0); issue(0, 1); CP_COMMIT();
        for (int c = 0; c < NC; c++) {
            CP_WAIT0();
            __syncthreads();
            bool more = (c + 1 < NC);
            compute_stage(sb + (c & 1) * STAGE_B, lane, wm, wn, W,
                          [&](int q) { if (more) issue(c + 1, q); });
            CP_COMMIT();
        }

        const float* bias = proj_b + (size_t)e * DH;
#pragma unroll
        for (int mi = 0; mi < 4; mi++) {
#pragma unroll
            for (int rh = 0; rh < 2; rh++) {
                int m = wm + mi * 16 + (lane >> 2) + rh * 8;
                if (m0 + m >= rows) continue;
                size_t slot = (size_t)row0 + m0 + m;
                float w = g_wt[slot];
#pragma unroll
                for (int nf = 0; nf < 4; nf++) {
                    int n = n0 + wn + nf * 8 + 2 * (lane & 3);
                    float2 bb = *(const float2*)(bias + n);
                    float v0 = w * (W.a[mi][nf][2 * rh + 0] + bb.x);
                    float v1 = w * (W.a[mi][nf][2 * rh + 1] + bb.y);
                    *(float2*)(g_O + slot * DH + n) = make_float2(v0, v1);
                }
            }
        }
    }
}

// ---------------- combine (+ counter reset for next call) --------------------
__global__ void combine_kernel(float* __restrict__ out) {
    if (blockIdx.x == 0 && threadIdx.x < NEXP) {
        g_count[threadIdx.x] = 0;
        g_cursor[threadIdx.x] = 0;
    }
    int idx = blockIdx.x * blockDim.x + threadIdx.x;
    const int DQ = DH / 4;
    if (idx >= NTOK * DQ) return;
    int t = idx / DQ;
    int dq = idx - t * DQ;
    int s0 = g_slot[t * 2 + 0];
    int s1 = g_slot[t * 2 + 1];
    const float4* o0 = (const float4*)(g_O + (size_t)s0 * DH) + dq;
    const float4* o1 = (const float4*)(g_O + (size_t)s1 * DH) + dq;
    float4 a = *o0, b = *o1;
    ((float4*)(out + (size_t)t * DH))[dq] =
        make_float4(a.x + b.x, a.y + b.y, a.z + b.z, a.w + b.w);
}

// ---------------- launch -----------------------------------------------------
extern "C" void kernel_launch(void* const* d_in, const int* in_sizes, int n_in,
                              void* d_out, int out_size) {
    const float* x      = (const float*)d_in[0];
    const float* gate_w = (const float*)d_in[1];
    const float* fc_w   = (const float*)d_in[2];
    const float* fc_b   = (const float*)d_in[3];
    const float* proj_w = (const float*)d_in[4];
    const float* proj_b = (const float*)d_in[5];

    float* out = (float*)d_out;
    float* out_logits =
        (out_size >= NTOK * DH + NTOK * NEXP) ? (out + (size_t)NTOK * DH) : nullptr;

    cudaFuncSetAttribute(gemm1_mma, cudaFuncAttributeMaxDynamicSharedMemorySize, SMEM_G1);
    cudaFuncSetAttribute(gemm2_mma, cudaFuncAttributeMaxDynamicSharedMemorySize, SMEM_G2);

    __nv_bfloat16 *fh, *fl, *ph, *pl;
    cudaGetSymbolAddress((void**)&fh, g_fcwT_hi);
    cudaGetSymbolAddress((void**)&fl, g_fcwT_lo);
    cudaGetSymbolAddress((void**)&ph, g_prjT_hi);
    cudaGetSymbolAddress((void**)&pl, g_prjT_lo);

    // ncu profiles the 4th launch -> keep it gemm1.
    router_split_kernel<<<NTOK / 8, 256>>>(x, gate_w, out_logits);                 // 1
    scan_scatter_kernel<<<1, 1024>>>();                                            // 2
    transpose_split_kernel<<<dim3(FH / 32, DH / 32, NEXP), dim3(32, 8)>>>(fc_w, fh, fl, DH, FH);   // 3
    gemm1_mma<<<PGRID, BLOCK, SMEM_G1>>>(fc_b);                                    // 4  <- profiled
    transpose_split_kernel<<<dim3(DH / 32, FH / 32, NEXP), dim3(32, 8)>>>(proj_w, ph, pl, FH, DH); // 5
    gemm2_mma<<<PGRID, BLOCK, SMEM_G2>>>(proj_b);                                  // 6
    combine_kernel<<<(NTOK * (DH / 4) + 255) / 256, 256>>>(out);                   // 7

    (void)n_in; (void)in_sizes;
}

// round 14
// speedup vs baseline: 1.8651x; 1.3013x over previous
#include <cuda_runtime.h>
#include <cuda_fp16.h>
#include <math.h>
#include <stdint.h>

// Problem constants
#define NEXP 8
#define TOPK 2
#define DH   1024
#define FH   4096
#define NTOK 4096
#define NSLOT (NTOK * TOPK)   // 8192

// ---------------- scratch (static __device__ — no allocations) -------------
__device__ __half g_X_hi[(size_t)NTOK * DH];
__device__ __half g_X_lo[(size_t)NTOK * DH];
__device__ __half g_fcwT[(size_t)NEXP * FH * DH];   // [e][n(F)][k(D)] fp16 RN
__device__ __half g_prjT[(size_t)NEXP * DH * FH];   // [e][n(D)][k(F)] fp16 RN
__device__ __half g_H_hi[(size_t)NSLOT * FH];
__device__ __half g_H_lo[(size_t)NSLOT * FH];
__device__ float g_O[(size_t)NSLOT * DH];
__device__ int   g_count[NEXP];     // statically zero; re-zeroed by combine
__device__ int   g_cursor[NEXP];
__device__ int   g_off[NEXP + 1];
__device__ int   g_eid[NSLOT];
__device__ float g_wk[NSLOT];
__device__ int   g_tok[NSLOT];
__device__ float g_wt[NSLOT];
__device__ int   g_slot[NSLOT];

// ---------------- generic-PTX helpers ---------------------------------------
__device__ __forceinline__ uint32_t smem_u32(const void* p) {
    uint32_t a;
    asm("{ .reg .u64 t; cvta.to.shared.u64 t, %1; cvt.u32.u64 %0, t; }" : "=r"(a) : "l"(p));
    return a;
}
__device__ __forceinline__ void cp16(uint32_t dst, const void* src, int srcsize) {
    asm volatile("cp.async.cg.shared.global [%0], [%1], 16, %2;"
                 :: "r"(dst), "l"(src), "r"(srcsize) : "memory");
}
#define CP_COMMIT() asm volatile("cp.async.commit_group;" ::: "memory")
#define CP_WAIT1()  asm volatile("cp.async.wait_group 1;" ::: "memory")

__device__ __forceinline__ void ldsm_x4(uint32_t* r, uint32_t addr) {
    asm volatile("ldmatrix.sync.aligned.m8n8.x4.shared.b16 {%0,%1,%2,%3}, [%4];"
                 : "=r"(r[0]), "=r"(r[1]), "=r"(r[2]), "=r"(r[3]) : "r"(addr));
}
// fp16 inputs, fp32 accumulate
__device__ __forceinline__ void mma16816(float* d, const uint32_t* a, uint32_t b0, uint32_t b1) {
    asm volatile(
        "mma.sync.aligned.m16n8k16.row.col.f32.f16.f16.f32 "
        "{%0,%1,%2,%3}, {%4,%5,%6,%7}, {%8,%9}, {%0,%1,%2,%3};"
        : "+f"(d[0]), "+f"(d[1]), "+f"(d[2]), "+f"(d[3])
        : "r"(a[0]), "r"(a[1]), "r"(a[2]), "r"(a[3]), "r"(b0), "r"(b1));
}

__device__ __forceinline__ float gelu_new(float v) {
    const float c = 0.7978845608028654f;
    float u = c * (v + 0.044715f * v * v * v);
    return 0.5f * v * (1.0f + tanhf(u));
}
__device__ __forceinline__ uint32_t pack2h(__half a, __half b) {
    return (uint32_t)__half_as_ushort(a) | ((uint32_t)__half_as_ushort(b) << 16);
}
// exact fp32 -> fp16 hi + fp16 lo split (x = hi + lo up to ~2^-22)
__device__ __forceinline__ void split4h(float4 v, uint2& hv, uint2& lv) {
    __half h0 = __float2half_rn(v.x), h1 = __float2half_rn(v.y);
    __half h2 = __float2half_rn(v.z), h3 = __float2half_rn(v.w);
    hv.x = pack2h(h0, h1); hv.y = pack2h(h2, h3);
    lv.x = pack2h(__float2half_rn(v.x - __half2float(h0)),
                  __float2half_rn(v.y - __half2float(h1)));
    lv.y = pack2h(__float2half_rn(v.z - __half2float(h2)),
                  __float2half_rn(v.w - __half2float(h3)));
}

// SMEM tile geometry: 128x128 CTA tile, K-stage = 32, row = 80 B, 3 slabs
#define SROW_B   80
#define OFF_AH   0
#define OFF_AL   10240              // 128 rows * 80
#define OFF_BH   20480
#define STAGE_B  30720              // Ah + Al + Bh
#define NSTAGE   3
#define SMEM_G1  (NSTAGE * STAGE_B + 512)   // 92672  -> 2 CTAs/SM
#define SMEM_G2  (NSTAGE * STAGE_B)
#define BLOCK    256

// ---------------- kernel 1: router + gate logits + x fp16 split -------------
__global__ void router_split_kernel(const float* __restrict__ x,
                                    const float* __restrict__ gate_w,
                                    float* __restrict__ out_logits) {
    int warp = (blockIdx.x * blockDim.x + threadIdx.x) >> 5;
    int lane = threadIdx.x & 31;
    if (warp >= NTOK) return;
    const float* xp = x + (size_t)warp * DH;
    float acc[NEXP];
#pragma unroll
    for (int e = 0; e < NEXP; e++) acc[e] = 0.0f;
#pragma unroll
    for (int i = 0; i < DH / 128; i++) {
        int d = i * 128 + lane * 4;
        float4 v = *(const float4*)(xp + d);
        uint2 hv, lv; split4h(v, hv, lv);
        *(uint2*)(g_X_hi + (size_t)warp * DH + d) = hv;
        *(uint2*)(g_X_lo + (size_t)warp * DH + d) = lv;
        const float* gw = gate_w + (size_t)d * NEXP;
#pragma unroll
        for (int e = 0; e < NEXP; e++)
            acc[e] += v.x * gw[e] + v.y * gw[NEXP + e]
                    + v.z * gw[2 * NEXP + e] + v.w * gw[3 * NEXP + e];
    }
#pragma unroll
    for (int e = 0; e < NEXP; e++)
#pragma unroll
        for (int o = 16; o > 0; o >>= 1)
            acc[e] += __shfl_xor_sync(0xffffffffu, acc[e], o);
    if (lane == 0) {
        if (out_logits)
#pragma unroll
            for (int e = 0; e < NEXP; e++) out_logits[warp * NEXP + e] = acc[e];
        int e0 = 0;
#pragma unroll
        for (int e = 1; e < NEXP; e++) if (acc[e] > acc[e0]) e0 = e;
        int e1 = (e0 == 0) ? 1 : 0;
#pragma unroll
        for (int e = 0; e < NEXP; e++) if (e != e0 && acc[e] > acc[e1]) e1 = e;
        float dlt = expf(acc[e1] - acc[e0]);
        float w0 = 1.0f / (1.0f + dlt);
        float w1 = dlt / (1.0f + dlt);
        g_eid[warp * 2 + 0] = e0; g_eid[warp * 2 + 1] = e1;
        g_wk [warp * 2 + 0] = w0; g_wk [warp * 2 + 1] = w1;
        atomicAdd(&g_count[e0], 1);
        atomicAdd(&g_count[e1], 1);
    }
}

// ---------------- kernel 2: fused scan + scatter (single block) --------------
__global__ void scan_scatter_kernel() {
    if (threadIdx.x == 0) {
        int acc = 0; g_off[0] = 0;
#pragma unroll
        for (int e = 0; e < NEXP; e++) { acc += g_count[e]; g_off[e + 1] = acc; }
    }
    __syncthreads();
    for (int t = threadIdx.x; t < NTOK; t += blockDim.x) {
#pragma unroll
        for (int k = 0; k < TOPK; k++) {
            int e = g_eid[t * 2 + k];
            int pos = g_off[e] + atomicAdd(&g_cursor[e], 1);
            g_tok[pos] = t;
            g_wt[pos]  = g_wk[t * 2 + k];
            g_slot[t * 2 + k] = pos;
        }
    }
}

// ------------- weight transpose + fp16 RN (single slab) ----------------------
__global__ __launch_bounds__(256)
void transpose_h_kernel(const float* __restrict__ src,
                        __half* __restrict__ dh, int K, int N) {
    __shared__ float t[32][33];
    int e = blockIdx.z;
    src += (size_t)e * K * N;
    dh  += (size_t)e * K * N;
    int n0 = blockIdx.x * 32, k0 = blockIdx.y * 32;
    int xx = threadIdx.x, yy = threadIdx.y;  // (32, 8)
    int tid = yy * 32 + xx;
#pragma unroll
    for (int r = 0; r < 4; r++) {
        int k = yy + r * 8;
        t[k][xx] = src[(size_t)(k0 + k) * N + n0 + xx];
    }
    __syncthreads();
#pragma unroll
    for (int it = 0; it < 2; it++) {
        int j = it * 256 + tid;
        int n = j >> 4, kp = j & 15;
        __half h0 = __float2half_rn(t[2 * kp][n]);
        __half h1 = __float2half_rn(t[2 * kp + 1][n]);
        *(uint32_t*)(dh + (size_t)(n0 + n) * K + k0 + 2 * kp) = pack2h(h0, h1);
    }
}

// ---------------- warp-level 64x32 2-pass compute over one 32-wide stage ----
struct WarpAcc { float a[4][4][4]; };   // [mi][nfrag][frag]

template <typename F>
__device__ __forceinline__ void compute_stage(uint32_t stb, int lane, int wm, int wn,
                                              WarpAcc& W, F&& issue_chunk) {
#pragma unroll
    for (int q = 0; q < 2; q++) {
        issue_chunk(q);                     // next-stage loads
        int kk = q * 16;
        uint32_t ah[4][4], al[4][4];
        uint32_t aoff = stb + OFF_AH
                      + (uint32_t)(wm + (lane & 15)) * SROW_B
                      + (uint32_t)(kk + ((lane >> 4) << 3)) * 2;
#pragma unroll
        for (int mi = 0; mi < 4; mi++) {
            ldsm_x4(ah[mi], aoff + mi * 16 * SROW_B);
            ldsm_x4(al[mi], aoff + mi * 16 * SROW_B + (OFF_AL - OFF_AH));
        }
        int bgrp = lane >> 3;
        uint32_t boff = stb + OFF_BH
                      + (uint32_t)(wn + (lane & 7) + ((bgrp & 2) << 2)) * SROW_B
                      + (uint32_t)(kk + ((bgrp & 1) << 3)) * 2;
#pragma unroll
        for (int p = 0; p < 2; p++) {           // n-frag pair (2p, 2p+1)
            uint32_t th[4];
            ldsm_x4(th, boff + p * 16 * SROW_B);
#pragma unroll
            for (int mi = 0; mi < 4; mi++) {
                mma16816(W.a[mi][2 * p],     ah[mi], th[0], th[1]);
                mma16816(W.a[mi][2 * p + 1], ah[mi], th[2], th[3]);
            }
#pragma unroll
            for (int mi = 0; mi < 4; mi++) {
                mma16816(W.a[mi][2 * p],     al[mi], th[0], th[1]);
                mma16816(W.a[mi][2 * p + 1], al[mi], th[2], th[3]);
            }
        }
    }
}

// ---------------- GEMM1: H = gelu(x@fc_w + b), 128x128 tile, 2 CTA/SM -------
__global__ __launch_bounds__(BLOCK, 2)
void gemm1_mma(const float* __restrict__ fc_b) {
    int e = blockIdx.z;
    int row0 = g_off[e];
    int rows = g_off[e + 1] - row0;
    int m0 = blockIdx.x * 128;
    if (m0 >= rows) return;
    int n0 = blockIdx.y * 128;

    extern __shared__ char smem[];
    uint32_t sb = smem_u32(smem);
    int tid = threadIdx.x, wid = tid >> 5, lane = tid & 31;

    int* s_tok = (int*)(smem + NSTAGE * STAGE_B);
    if (tid < 128) s_tok[tid] = (m0 + tid < rows) ? g_tok[row0 + m0 + tid] : -1;
    __syncthreads();

    const __half* B = g_fcwT + (size_t)e * FH * DH + (size_t)n0 * DH;
    const int NC = DH / 32;   // 32 stages

    // chunk q of stage c: q0 = Ah + Al (4 cp16/thr), q1 = Bh (2 cp16/thr)
    auto issue = [&](int c, int q) {
        uint32_t stb = sb + (c % NSTAGE) * STAGE_B;
        int kt = c * 32;
        if (q == 0) {
#pragma unroll
            for (int i = 0; i < 4; i++) {
                int u = tid + (i & 1) * BLOCK;
                int row = u >> 2, ch = u & 3;
                int which = i >> 1;   // 0 hi, 1 lo
                uint32_t dst = stb + (which ? OFF_AL : OFF_AH) + row * SROW_B + ch * 16;
                int t = s_tok[row];
                const __half* base = which ? g_X_lo : g_X_hi;
                cp16(dst, base + (size_t)(t < 0 ? 0 : t) * DH + kt + ch * 8, t < 0 ? 0 : 16);
            }
        } else {
#pragma unroll
            for (int i = 0; i < 2; i++) {
                int u = tid + i * BLOCK;
                int row = u >> 2, ch = u & 3;
                uint32_t dst = stb + OFF_BH + row * SROW_B + ch * 16;
                cp16(dst, B + (size_t)row * DH + kt + ch * 8, 16);
            }
        }
    };

    WarpAcc W;
#pragma unroll
    for (int mi = 0; mi < 4; mi++)
#pragma unroll
        for (int nf = 0; nf < 4; nf++)
#pragma unroll
            for (int r = 0; r < 4; r++) W.a[mi][nf][r] = 0.0f;

    int wm = (wid & 1) * 64, wn = (wid >> 1) * 32;

    issue(0, 0); issue(0, 1); CP_COMMIT();
    issue(1, 0); issue(1, 1); CP_COMMIT();
    for (int c = 0; c < NC; c++) {
        CP_WAIT1();
        __syncthreads();
        bool more = (c + 2 < NC);
        compute_stage(sb + (c % NSTAGE) * STAGE_B, lane, wm, wn, W,
                      [&](int q) { if (more) issue(c + 2, q); });
        CP_COMMIT();
    }

    const float* bias = fc_b + (size_t)e * FH;
#pragma unroll
    for (int mi = 0; mi < 4; mi++) {
#pragma unroll
        for (int rh = 0; rh < 2; rh++) {
            int m = wm + mi * 16 + (lane >> 2) + rh * 8;
            if (m0 + m >= rows) continue;
            size_t slot = (size_t)row0 + m0 + m;
#pragma unroll
            for (int nf = 0; nf < 4; nf++) {
                int n = n0 + wn + nf * 8 + 2 * (lane & 3);
                float2 bb = *(const float2*)(bias + n);
                float v0 = gelu_new(W.a[mi][nf][2 * rh + 0] + bb.x);
                float v1 = gelu_new(W.a[mi][nf][2 * rh + 1] + bb.y);
                __half h0 = __float2half_rn(v0), h1 = __float2half_rn(v1);
                __half l0 = __float2half_rn(v0 - __half2float(h0));
                __half l1 = __float2half_rn(v1 - __half2float(h1));
                *(uint32_t*)(g_H_hi + slot * FH + n) = pack2h(h0, h1);
                *(uint32_t*)(g_H_lo + slot * FH + n) = pack2h(l0, l1);
            }
        }
    }
}

// ---------------- GEMM2: O = wt * (H@proj_w + b), 128x128 tile, 2 CTA/SM ----
__global__ __launch_bounds__(BLOCK, 2)
void gemm2_mma(const float* __restrict__ proj_b) {
    int e = blockIdx.z;
    int row0 = g_off[e];
    int rows = g_off[e + 1] - row0;
    int m0 = blockIdx.x * 128;
    if (m0 >= rows) return;
    int n0 = blockIdx.y * 128;

    extern __shared__ char smem[];
    uint32_t sb = smem_u32(smem);
    int tid = threadIdx.x, wid = tid >> 5, lane = tid & 31;

    const __half* B = g_prjT + (size_t)e * DH * FH + (size_t)n0 * FH;
    const int NC = FH / 32;   // 128 stages

    auto issue = [&](int c, int q) {
        uint32_t stb = sb + (c % NSTAGE) * STAGE_B;
        int kt = c * 32;
        if (q == 0) {
#pragma unroll
            for (int i = 0; i < 4; i++) {
                int u = tid + (i & 1) * BLOCK;
                int row = u >> 2, ch = u & 3;
                int which = i >> 1;
                uint32_t dst = stb + (which ? OFF_AL : OFF_AH) + row * SROW_B + ch * 16;
                bool ok = (m0 + row) < rows;
                size_t slot = (size_t)row0 + m0 + (ok ? row : 0);
                const __half* base = which ? g_H_lo : g_H_hi;
                cp16(dst, base + slot * FH + kt + ch * 8, ok ? 16 : 0);
            }
        } else {
#pragma unroll
            for (int i = 0; i < 2; i++) {
                int u = tid + i * BLOCK;
                int row = u >> 2, ch = u & 3;
                uint32_t dst = stb + OFF_BH + row * SROW_B + ch * 16;
                cp16(dst, B + (size_t)row * FH + kt + ch * 8, 16);
            }
        }
    };

    WarpAcc W;
#pragma unroll
    for (int mi = 0; mi < 4; mi++)
#pragma unroll
        for (int nf = 0; nf < 4; nf++)
#pragma unroll
            for (int r = 0; r < 4; r++) W.a[mi][nf][r] = 0.0f;

    int wm = (wid & 1) * 64, wn = (wid >> 1) * 32;

    issue(0, 0); issue(0, 1); CP_COMMIT();
    issue(1, 0); issue(1, 1); CP_COMMIT();
    for (int c = 0; c < NC; c++) {
        CP_WAIT1();
        __syncthreads();
        bool more = (c + 2 < NC);
        compute_stage(sb + (c % NSTAGE) * STAGE_B, lane, wm, wn, W,
                      [&](int q) { if (more) issue(c + 2, q); });
        CP_COMMIT();
    }

    const float* bias = proj_b + (size_t)e * DH;
#pragma unroll
    for (int mi = 0; mi < 4; mi++) {
#pragma unroll
        for (int rh = 0; rh < 2; rh++) {
            int m = wm + mi * 16 + (lane >> 2) + rh * 8;
            if (m0 + m >= rows) continue;
            size_t slot = (size_t)row0 + m0 + m;
            float w = g_wt[slot];
#pragma unroll
            for (int nf = 0; nf < 4; nf++) {
                int n = n0 + wn + nf * 8 + 2 * (lane & 3);
                float2 bb = *(const float2*)(bias + n);
                float v0 = w * (W.a[mi][nf][2 * rh + 0] + bb.x);
                float v1 = w * (W.a[mi][nf][2 * rh + 1] + bb.y);
                *(float2*)(g_O + slot * DH + n) = make_float2(v0, v1);
            }
        }
    }
}

// ---------------- combine (+ counter reset for next call) --------------------
__global__ void combine_kernel(float* __restrict__ out) {
    if (blockIdx.x == 0 && threadIdx.x < NEXP) {
        g_count[threadIdx.x] = 0;
        g_cursor[threadIdx.x] = 0;
    }
    int idx = blockIdx.x * blockDim.x + threadIdx.x;
    const int DQ = DH / 4;
    if (idx >= NTOK * DQ) return;
    int t = idx / DQ;
    int dq = idx - t * DQ;
    int s0 = g_slot[t * 2 + 0];
    int s1 = g_slot[t * 2 + 1];
    const float4* o0 = (const float4*)(g_O + (size_t)s0 * DH) + dq;
    const float4* o1 = (const float4*)(g_O + (size_t)s1 * DH) + dq;
    float4 a = *o0, b = *o1;
    ((float4*)(out + (size_t)t * DH))[dq] =
        make_float4(a.x + b.x, a.y + b.y, a.z + b.z, a.w + b.w);
}

// ---------------- launch -----------------------------------------------------
extern "C" void kernel_launch(void* const* d_in, const int* in_sizes, int n_in,
                              void* d_out, int out_size) {
    const float* x      = (const float*)d_in[0];
    const float* gate_w = (const float*)d_in[1];
    const float* fc_w   = (const float*)d_in[2];
    const float* fc_b   = (const float*)d_in[3];
    const float* proj_w = (const float*)d_in[4];
    const float* proj_b = (const float*)d_in[5];

    float* out = (float*)d_out;
    float* out_logits =
        (out_size >= NTOK * DH + NTOK * NEXP) ? (out + (size_t)NTOK * DH) : nullptr;

    cudaFuncSetAttribute(gemm1_mma, cudaFuncAttributeMaxDynamicSharedMemorySize, SMEM_G1);
    cudaFuncSetAttribute(gemm2_mma, cudaFuncAttributeMaxDynamicSharedMemorySize, SMEM_G2);

    __half *fh, *ph;
    cudaGetSymbolAddress((void**)&fh, g_fcwT);
    cudaGetSymbolAddress((void**)&ph, g_prjT);

    // ncu profiles the 4th launch -> keep it gemm1.
    router_split_kernel<<<NTOK / 8, 256>>>(x, gate_w, out_logits);                 // 1
    scan_scatter_kernel<<<1, 1024>>>();                                            // 2
    transpose_h_kernel<<<dim3(FH / 32, DH / 32, NEXP), dim3(32, 8)>>>(fc_w, fh, DH, FH);   // 3
    gemm1_mma<<<dim3(NTOK / 128, FH / 128, NEXP), BLOCK, SMEM_G1>>>(fc_b);         // 4  <- profiled
    transpose_h_kernel<<<dim3(DH / 32, FH / 32, NEXP), dim3(32, 8)>>>(proj_w, ph, FH, DH); // 5
    gemm2_mma<<<dim3(NTOK / 128, DH / 128, NEXP), BLOCK, SMEM_G2>>>(proj_b);       // 6
    combine_kernel<<<(NTOK * (DH / 4) + 255) / 256, 256>>>(out);                   // 7

    (void)n_in; (void)in_sizes;
}

// round 15
// speedup vs baseline: 2.9483x; 1.5808x over previous
#include <cuda_runtime.h>
#include <cuda_fp16.h>
#include <math.h>
#include <stdint.h>

// Problem constants
#define NEXP 8
#define TOPK 2
#define DH   1024
#define FH   4096
#define NTOK 4096
#define NSLOT (NTOK * TOPK)   // 8192

// ---------------- scratch (static __device__ — no allocations) -------------
__device__ __half g_X[(size_t)NTOK * DH];           // fp16 RN
__device__ __half g_fcwT[(size_t)NEXP * FH * DH];   // [e][n(F)][k(D)] fp16 RN
__device__ __half g_prjT[(size_t)NEXP * DH * FH];   // [e][n(D)][k(F)] fp16 RN
__device__ __half g_H[(size_t)NSLOT * FH];          // fp16 RN
__device__ float g_O[(size_t)NSLOT * DH];
__device__ int   g_count[NEXP];     // statically zero; re-zeroed by combine
__device__ int   g_cursor[NEXP];
__device__ int   g_off[NEXP + 1];
__device__ int   g_eid[NSLOT];
__device__ float g_wk[NSLOT];
__device__ int   g_tok[NSLOT];
__device__ float g_wt[NSLOT];
__device__ int   g_slot[NSLOT];

// ---------------- generic-PTX helpers ---------------------------------------
__device__ __forceinline__ uint32_t smem_u32(const void* p) {
    uint32_t a;
    asm("{ .reg .u64 t; cvta.to.shared.u64 t, %1; cvt.u32.u64 %0, t; }" : "=r"(a) : "l"(p));
    return a;
}
__device__ __forceinline__ void cp16(uint32_t dst, const void* src, int srcsize) {
    asm volatile("cp.async.cg.shared.global [%0], [%1], 16, %2;"
                 :: "r"(dst), "l"(src), "r"(srcsize) : "memory");
}
#define CP_COMMIT() asm volatile("cp.async.commit_group;" ::: "memory")
#define CP_WAIT1()  asm volatile("cp.async.wait_group 1;" ::: "memory")

__device__ __forceinline__ void ldsm_x4(uint32_t* r, uint32_t addr) {
    asm volatile("ldmatrix.sync.aligned.m8n8.x4.shared.b16 {%0,%1,%2,%3}, [%4];"
                 : "=r"(r[0]), "=r"(r[1]), "=r"(r[2]), "=r"(r[3]) : "r"(addr));
}
// fp16 inputs, fp32 accumulate
__device__ __forceinline__ void mma16816(float* d, const uint32_t* a, uint32_t b0, uint32_t b1) {
    asm volatile(
        "mma.sync.aligned.m16n8k16.row.col.f32.f16.f16.f32 "
        "{%0,%1,%2,%3}, {%4,%5,%6,%7}, {%8,%9}, {%0,%1,%2,%3};"
        : "+f"(d[0]), "+f"(d[1]), "+f"(d[2]), "+f"(d[3])
        : "r"(a[0]), "r"(a[1]), "r"(a[2]), "r"(a[3]), "r"(b0), "r"(b1));
}

__device__ __forceinline__ float gelu_new(float v) {
    const float c = 0.7978845608028654f;
    float u = c * (v + 0.044715f * v * v * v);
    return 0.5f * v * (1.0f + tanhf(u));
}
__device__ __forceinline__ uint32_t pack2h(__half a, __half b) {
    return (uint32_t)__half_as_ushort(a) | ((uint32_t)__half_as_ushort(b) << 16);
}

// SMEM tile geometry: 128x128 CTA tile, K-stage = 32, row = 80 B, 2 slabs
#define SROW_B   80
#define OFF_A    0
#define OFF_B    10240              // 128 rows * 80
#define STAGE_B  20480              // A + B
#define NSTAGE   3
#define SMEM_G1  (NSTAGE * STAGE_B + 512)   // 61952  -> 2 CTAs/SM
#define SMEM_G2  (NSTAGE * STAGE_B)
#define BLOCK    256

// ---------------- kernel 1: router + gate logits + x fp16 cast --------------
__global__ void router_split_kernel(const float* __restrict__ x,
                                    const float* __restrict__ gate_w,
                                    float* __restrict__ out_logits) {
    int warp = (blockIdx.x * blockDim.x + threadIdx.x) >> 5;
    int lane = threadIdx.x & 31;
    if (warp >= NTOK) return;
    const float* xp = x + (size_t)warp * DH;
    float acc[NEXP];
#pragma unroll
    for (int e = 0; e < NEXP; e++) acc[e] = 0.0f;
#pragma unroll
    for (int i = 0; i < DH / 128; i++) {
        int d = i * 128 + lane * 4;
        float4 v = *(const float4*)(xp + d);
        uint2 hv;
        hv.x = pack2h(__float2half_rn(v.x), __float2half_rn(v.y));
        hv.y = pack2h(__float2half_rn(v.z), __float2half_rn(v.w));
        *(uint2*)(g_X + (size_t)warp * DH + d) = hv;
        const float* gw = gate_w + (size_t)d * NEXP;
#pragma unroll
        for (int e = 0; e < NEXP; e++)
            acc[e] += v.x * gw[e] + v.y * gw[NEXP + e]
                    + v.z * gw[2 * NEXP + e] + v.w * gw[3 * NEXP + e];
    }
#pragma unroll
    for (int e = 0; e < NEXP; e++)
#pragma unroll
        for (int o = 16; o > 0; o >>= 1)
            acc[e] += __shfl_xor_sync(0xffffffffu, acc[e], o);
    if (lane == 0) {
        if (out_logits)
#pragma unroll
            for (int e = 0; e < NEXP; e++) out_logits[warp * NEXP + e] = acc[e];
        int e0 = 0;
#pragma unroll
        for (int e = 1; e < NEXP; e++) if (acc[e] > acc[e0]) e0 = e;
        int e1 = (e0 == 0) ? 1 : 0;
#pragma unroll
        for (int e = 0; e < NEXP; e++) if (e != e0 && acc[e] > acc[e1]) e1 = e;
        float dlt = expf(acc[e1] - acc[e0]);
        float w0 = 1.0f / (1.0f + dlt);
        float w1 = dlt / (1.0f + dlt);
        g_eid[warp * 2 + 0] = e0; g_eid[warp * 2 + 1] = e1;
        g_wk [warp * 2 + 0] = w0; g_wk [warp * 2 + 1] = w1;
        atomicAdd(&g_count[e0], 1);
        atomicAdd(&g_count[e1], 1);
    }
}

// ---------------- kernel 2: fused scan + scatter (single block) --------------
__global__ void scan_scatter_kernel() {
    if (threadIdx.x == 0) {
        int acc = 0; g_off[0] = 0;
#pragma unroll
        for (int e = 0; e < NEXP; e++) { acc += g_count[e]; g_off[e + 1] = acc; }
    }
    __syncthreads();
    for (int t = threadIdx.x; t < NTOK; t += blockDim.x) {
#pragma unroll
        for (int k = 0; k < TOPK; k++) {
            int e = g_eid[t * 2 + k];
            int pos = g_off[e] + atomicAdd(&g_cursor[e], 1);
            g_tok[pos] = t;
            g_wt[pos]  = g_wk[t * 2 + k];
            g_slot[t * 2 + k] = pos;
        }
    }
}

// ------------- weight transpose + fp16 RN (single slab) ----------------------
__global__ __launch_bounds__(256)
void transpose_h_kernel(const float* __restrict__ src,
                        __half* __restrict__ dh, int K, int N) {
    __shared__ float t[32][33];
    int e = blockIdx.z;
    src += (size_t)e * K * N;
    dh  += (size_t)e * K * N;
    int n0 = blockIdx.x * 32, k0 = blockIdx.y * 32;
    int xx = threadIdx.x, yy = threadIdx.y;  // (32, 8)
    int tid = yy * 32 + xx;
#pragma unroll
    for (int r = 0; r < 4; r++) {
        int k = yy + r * 8;
        t[k][xx] = src[(size_t)(k0 + k) * N + n0 + xx];
    }
    __syncthreads();
#pragma unroll
    for (int it = 0; it < 2; it++) {
        int j = it * 256 + tid;
        int n = j >> 4, kp = j & 15;
        __half h0 = __float2half_rn(t[2 * kp][n]);
        __half h1 = __float2half_rn(t[2 * kp + 1][n]);
        *(uint32_t*)(dh + (size_t)(n0 + n) * K + k0 + 2 * kp) = pack2h(h0, h1);
    }
}

// ---------------- warp-level 64x32 single-pass compute over 32-wide stage ---
struct WarpAcc { float a[4][4][4]; };   // [mi][nfrag][frag]

template <typename F>
__device__ __forceinline__ void compute_stage(uint32_t stb, int lane, int wm, int wn,
                                              WarpAcc& W, F&& issue_chunk) {
#pragma unroll
    for (int q = 0; q < 2; q++) {
        issue_chunk(q);                     // next-stage loads (2 cp16/thread)
        int kk = q * 16;
        uint32_t ah[4][4];
        uint32_t aoff = stb + OFF_A
                      + (uint32_t)(wm + (lane & 15)) * SROW_B
                      + (uint32_t)(kk + ((lane >> 4) << 3)) * 2;
#pragma unroll
        for (int mi = 0; mi < 4; mi++)
            ldsm_x4(ah[mi], aoff + mi * 16 * SROW_B);
        int bgrp = lane >> 3;
        uint32_t boff = stb + OFF_B
                      + (uint32_t)(wn + (lane & 7) + ((bgrp & 2) << 2)) * SROW_B
                      + (uint32_t)(kk + ((bgrp & 1) << 3)) * 2;
#pragma unroll
        for (int p = 0; p < 2; p++) {           // n-frag pair (2p, 2p+1)
            uint32_t th[4];
            ldsm_x4(th, boff + p * 16 * SROW_B);
#pragma unroll
            for (int mi = 0; mi < 4; mi++) {
                mma16816(W.a[mi][2 * p],     ah[mi], th[0], th[1]);
                mma16816(W.a[mi][2 * p + 1], ah[mi], th[2], th[3]);
            }
        }
    }
}

// ---------------- GEMM1: H = gelu(x@fc_w + b), 128x128 tile, 2 CTA/SM -------
__global__ __launch_bounds__(BLOCK, 2)
void gemm1_mma(const float* __restrict__ fc_b) {
    int e = blockIdx.z;
    int row0 = g_off[e];
    int rows = g_off[e + 1] - row0;
    int m0 = blockIdx.x * 128;
    if (m0 >= rows) return;
    int n0 = blockIdx.y * 128;

    extern __shared__ char smem[];
    uint32_t sb = smem_u32(smem);
    int tid = threadIdx.x, wid = tid >> 5, lane = tid & 31;

    int* s_tok = (int*)(smem + NSTAGE * STAGE_B);
    if (tid < 128) s_tok[tid] = (m0 + tid < rows) ? g_tok[row0 + m0 + tid] : -1;
    __syncthreads();

    const __half* B = g_fcwT + (size_t)e * FH * DH + (size_t)n0 * DH;
    const int NC = DH / 32;   // 32 stages

    // chunk q of stage c: q0 = A (2 cp16/thr), q1 = B (2 cp16/thr)
    auto issue = [&](int c, int q) {
        uint32_t stb = sb + (c % NSTAGE) * STAGE_B;
        int kt = c * 32;
        if (q == 0) {
#pragma unroll
            for (int i = 0; i < 2; i++) {
                int u = tid + i * BLOCK;
                int row = u >> 2, ch = u & 3;
                uint32_t dst = stb + OFF_A + row * SROW_B + ch * 16;
                int t = s_tok[row];
                cp16(dst, g_X + (size_t)(t < 0 ? 0 : t) * DH + kt + ch * 8, t < 0 ? 0 : 16);
            }
        } else {
#pragma unroll
            for (int i = 0; i < 2; i++) {
                int u = tid + i * BLOCK;
                int row = u >> 2, ch = u & 3;
                uint32_t dst = stb + OFF_B + row * SROW_B + ch * 16;
                cp16(dst, B + (size_t)row * DH + kt + ch * 8, 16);
            }
        }
    };

    WarpAcc W;
#pragma unroll
    for (int mi = 0; mi < 4; mi++)
#pragma unroll
        for (int nf = 0; nf < 4; nf++)
#pragma unroll
            for (int r = 0; r < 4; r++) W.a[mi][nf][r] = 0.0f;

    int wm = (wid & 1) * 64, wn = (wid >> 1) * 32;

    issue(0, 0); issue(0, 1); CP_COMMIT();
    issue(1, 0); issue(1, 1); CP_COMMIT();
    for (int c = 0; c < NC; c++) {
        CP_WAIT1();
        __syncthreads();
        bool more = (c + 2 < NC);
        compute_stage(sb + (c % NSTAGE) * STAGE_B, lane, wm, wn, W,
                      [&](int q) { if (more) issue(c + 2, q); });
        CP_COMMIT();
    }

    const float* bias = fc_b + (size_t)e * FH;
#pragma unroll
    for (int mi = 0; mi < 4; mi++) {
#pragma unroll
        for (int rh = 0; rh < 2; rh++) {
            int m = wm + mi * 16 + (lane >> 2) + rh * 8;
            if (m0 + m >= rows) continue;
            size_t slot = (size_t)row0 + m0 + m;
#pragma unroll
            for (int nf = 0; nf < 4; nf++) {
                int n = n0 + wn + nf * 8 + 2 * (lane & 3);
                float2 bb = *(const float2*)(bias + n);
                float v0 = gelu_new(W.a[mi][nf][2 * rh + 0] + bb.x);
                float v1 = gelu_new(W.a[mi][nf][2 * rh + 1] + bb.y);
                *(uint32_t*)(g_H + slot * FH + n) =
                    pack2h(__float2half_rn(v0), __float2half_rn(v1));
            }
        }
    }
}

// ---------------- GEMM2: O = wt * (H@proj_w + b), 128x128 tile, 2 CTA/SM ----
__global__ __launch_bounds__(BLOCK, 2)
void gemm2_mma(const float* __restrict__ proj_b) {
    int e = blockIdx.z;
    int row0 = g_off[e];
    int rows = g_off[e + 1] - row0;
    int m0 = blockIdx.x * 128;
    if (m0 >= rows) return;
    int n0 = blockIdx.y * 128;

    extern __shared__ char smem[];
    uint32_t sb = smem_u32(smem);
    int tid = threadIdx.x, wid = tid >> 5, lane = tid & 31;

    const __half* B = g_prjT + (size_t)e * DH * FH + (size_t)n0 * FH;
    const int NC = FH / 32;   // 128 stages

    auto issue = [&](int c, int q) {
        uint32_t stb = sb + (c % NSTAGE) * STAGE_B;
        int kt = c * 32;
        if (q == 0) {
#pragma unroll
            for (int i = 0; i < 2; i++) {
                int u = tid + i * BLOCK;
                int row = u >> 2, ch = u & 3;
                uint32_t dst = stb + OFF_A + row * SROW_B + ch * 16;
                bool ok = (m0 + row) < rows;
                size_t slot = (size_t)row0 + m0 + (ok ? row : 0);
                cp16(dst, g_H + slot * FH + kt + ch * 8, ok ? 16 : 0);
            }
        } else {
#pragma unroll
            for (int i = 0; i < 2; i++) {
                int u = tid + i * BLOCK;
                int row = u >> 2, ch = u & 3;
                uint32_t dst = stb + OFF_B + row * SROW_B + ch * 16;
                cp16(dst, B + (size_t)row * FH + kt + ch * 8, 16);
            }
        }
    };

    WarpAcc W;
#pragma unroll
    for (int mi = 0; mi < 4; mi++)
#pragma unroll
        for (int nf = 0; nf < 4; nf++)
#pragma unroll
            for (int r = 0; r < 4; r++) W.a[mi][nf][r] = 0.0f;

    int wm = (wid & 1) * 64, wn = (wid >> 1) * 32;

    issue(0, 0); issue(0, 1); CP_COMMIT();
    issue(1, 0); issue(1, 1); CP_COMMIT();
    for (int c = 0; c < NC; c++) {
        CP_WAIT1();
        __syncthreads();
        bool more = (c + 2 < NC);
        compute_stage(sb + (c % NSTAGE) * STAGE_B, lane, wm, wn, W,
                      [&](int q) { if (more) issue(c + 2, q); });
        CP_COMMIT();
    }

    const float* bias = proj_b + (size_t)e * DH;
#pragma unroll
    for (int mi = 0; mi < 4; mi++) {
#pragma unroll
        for (int rh = 0; rh < 2; rh++) {
            int m = wm + mi * 16 + (lane >> 2) + rh * 8;
            if (m0 + m >= rows) continue;
            size_t slot = (size_t)row0 + m0 + m;
            float w = g_wt[slot];
#pragma unroll
            for (int nf = 0; nf < 4; nf++) {
                int n = n0 + wn + nf * 8 + 2 * (lane & 3);
                float2 bb = *(const float2*)(bias + n);
                float v0 = w * (W.a[mi][nf][2 * rh + 0] + bb.x);
                float v1 = w * (W.a[mi][nf][2 * rh + 1] + bb.y);
                *(float2*)(g_O + slot * DH + n) = make_float2(v0, v1);
            }
        }
    }
}

// ---------------- combine (+ counter reset for next call) --------------------
__global__ void combine_kernel(float* __restrict__ out) {
    if (blockIdx.x == 0 && threadIdx.x < NEXP) {
        g_count[threadIdx.x] = 0;
        g_cursor[threadIdx.x] = 0;
    }
    int idx = blockIdx.x * blockDim.x + threadIdx.x;
    const int DQ = DH / 4;
    if (idx >= NTOK * DQ) return;
    int t = idx / DQ;
    int dq = idx - t * DQ;
    int s0 = g_slot[t * 2 + 0];
    int s1 = g_slot[t * 2 + 1];
    const float4* o0 = (const float4*)(g_O + (size_t)s0 * DH) + dq;
    const float4* o1 = (const float4*)(g_O + (size_t)s1 * DH) + dq;
    float4 a = *o0, b = *o1;
    ((float4*)(out + (size_t)t * DH))[dq] =
        make_float4(a.x + b.x, a.y + b.y, a.z + b.z, a.w + b.w);
}

// ---------------- launch -----------------------------------------------------
extern "C" void kernel_launch(void* const* d_in, const int* in_sizes, int n_in,
                              void* d_out, int out_size) {
    const float* x      = (const float*)d_in[0];
    const float* gate_w = (const float*)d_in[1];
    const float* fc_w   = (const float*)d_in[2];
    const float* fc_b   = (const float*)d_in[3];
    const float* proj_w = (const float*)d_in[4];
    const float* proj_b = (const float*)d_in[5];

    float* out = (float*)d_out;
    float* out_logits =
        (out_size >= NTOK * DH + NTOK * NEXP) ? (out + (size_t)NTOK * DH) : nullptr;

    cudaFuncSetAttribute(gemm1_mma, cudaFuncAttributeMaxDynamicSharedMemorySize, SMEM_G1);
    cudaFuncSetAttribute(gemm2_mma, cudaFuncAttributeMaxDynamicSharedMemorySize, SMEM_G2);

    __half *fh, *ph;
    cudaGetSymbolAddress((void**)&fh, g_fcwT);
    cudaGetSymbolAddress((void**)&ph, g_prjT);

    // ncu profiles the 4th launch -> keep it gemm1.
    router_split_kernel<<<NTOK / 8, 256>>>(x, gate_w, out_logits);                 // 1
    scan_scatter_kernel<<<1, 1024>>>();                                            // 2
    transpose_h_kernel<<<dim3(FH / 32, DH / 32, NEXP), dim3(32, 8)>>>(fc_w, fh, DH, FH);   // 3
    gemm1_mma<<<dim3(NTOK / 128, FH / 128, NEXP), BLOCK, SMEM_G1>>>(fc_b);         // 4  <- profiled
    transpose_h_kernel<<<dim3(DH / 32, FH / 32, NEXP), dim3(32, 8)>>>(proj_w, ph, FH, DH); // 5
    gemm2_mma<<<dim3(NTOK / 128, DH / 128, NEXP), BLOCK, SMEM_G2>>>(proj_b);       // 6
    combine_kernel<<<(NTOK * (DH / 4) + 255) / 256, 256>>>(out);                   // 7

    (void)n_in; (void)in_sizes;
}

// round 16
// speedup vs baseline: 3.2337x; 1.0968x over previous
#include <cuda_runtime.h>
#include <cuda_fp16.h>
#include <math.h>
#include <stdint.h>

// Problem constants
#define NEXP 8
#define TOPK 2
#define DH   1024
#define FH   4096
#define NTOK 4096
#define NSLOT (NTOK * TOPK)   // 8192

// ---------------- scratch (static __device__ — no allocations) -------------
__device__ __half g_X[(size_t)NTOK * DH];           // fp16 RN
__device__ __half g_fcwT[(size_t)NEXP * FH * DH];   // [e][n(F)][k(D)] fp16 RN
__device__ __half g_prjT[(size_t)NEXP * DH * FH];   // [e][n(D)][k(F)] fp16 RN
__device__ __half g_H[(size_t)NSLOT * FH];          // fp16 RN
__device__ float g_O[(size_t)NSLOT * DH];
__device__ int   g_count[NEXP];     // statically zero; re-zeroed by combine
__device__ int   g_cursor[NEXP];
__device__ int   g_off[NEXP + 1];
__device__ int   g_eid[NSLOT];
__device__ float g_wk[NSLOT];
__device__ int   g_tok[NSLOT];
__device__ float g_wt[NSLOT];
__device__ int   g_slot[NSLOT];

// ---------------- generic-PTX helpers ---------------------------------------
__device__ __forceinline__ uint32_t smem_u32(const void* p) {
    uint32_t a;
    asm("{ .reg .u64 t; cvta.to.shared.u64 t, %1; cvt.u32.u64 %0, t; }" : "=r"(a) : "l"(p));
    return a;
}
__device__ __forceinline__ void cp16(uint32_t dst, const void* src, int srcsize) {
    asm volatile("cp.async.cg.shared.global [%0], [%1], 16, %2;"
                 :: "r"(dst), "l"(src), "r"(srcsize) : "memory");
}
#define CP_COMMIT() asm volatile("cp.async.commit_group;" ::: "memory")
#define CP_WAIT0()  asm volatile("cp.async.wait_group 0;" ::: "memory")

__device__ __forceinline__ void ldsm_x4(uint32_t* r, uint32_t addr) {
    asm volatile("ldmatrix.sync.aligned.m8n8.x4.shared.b16 {%0,%1,%2,%3}, [%4];"
                 : "=r"(r[0]), "=r"(r[1]), "=r"(r[2]), "=r"(r[3]) : "r"(addr));
}
// fp16 inputs, fp32 accumulate
__device__ __forceinline__ void mma16816(float* d, const uint32_t* a, uint32_t b0, uint32_t b1) {
    asm volatile(
        "mma.sync.aligned.m16n8k16.row.col.f32.f16.f16.f32 "
        "{%0,%1,%2,%3}, {%4,%5,%6,%7}, {%8,%9}, {%0,%1,%2,%3};"
        : "+f"(d[0]), "+f"(d[1]), "+f"(d[2]), "+f"(d[3])
        : "r"(a[0]), "r"(a[1]), "r"(a[2]), "r"(a[3]), "r"(b0), "r"(b1));
}

__device__ __forceinline__ float gelu_new(float v) {
    const float c = 0.7978845608028654f;
    float u = c * (v + 0.044715f * v * v * v);
    return 0.5f * v * (1.0f + tanhf(u));
}
__device__ __forceinline__ uint32_t pack2h(__half a, __half b) {
    return (uint32_t)__half_as_ushort(a) | ((uint32_t)__half_as_ushort(b) << 16);
}

// SMEM tile geometry: 128x128 CTA tile, K-stage = 64, row = 144 B (128+16 pad)
#define SROW_B   144
#define OFF_A    0
#define OFF_B    18432              // 128 rows * 144
#define STAGE_B  36864              // A + B
#define NSTAGE   2
#define SMEM_G1  (NSTAGE * STAGE_B + 512)   // 74240  -> 2 CTAs/SM
#define SMEM_G2  (NSTAGE * STAGE_B)
#define BLOCK    256

// prep kernel block ranges
#define NB_ROUTER 512                        // NTOK/8 warps-of-routing
#define NB_FC     (128 * 32 * NEXP)          // (FH/32)*(DH/32)*E = 32768
#define NB_PJ     (32 * 128 * NEXP)          // (DH/32)*(FH/32)*E = 32768
#define NB_PREP   (NB_ROUTER + NB_FC + NB_PJ)

// ---------------- transpose helper (device) ----------------------------------
__device__ __forceinline__ void transpose_tile(const float* __restrict__ src,
                                               __half* __restrict__ dst,
                                               int K, int N, int n0, int k0,
                                               float* tbuf /*32*33*/) {
    int tid = threadIdx.x;
    int xx = tid & 31, yy = tid >> 5;   // (32, 8)
#pragma unroll
    for (int r = 0; r < 4; r++) {
        int k = yy + r * 8;
        tbuf[k * 33 + xx] = src[(size_t)(k0 + k) * N + n0 + xx];
    }
    __syncthreads();
#pragma unroll
    for (int it = 0; it < 2; it++) {
        int j = it * 256 + tid;
        int n = j >> 4, kp = j & 15;
        __half h0 = __float2half_rn(tbuf[(2 * kp) * 33 + n]);
        __half h1 = __float2half_rn(tbuf[(2 * kp + 1) * 33 + n]);
        *(uint32_t*)(dst + (size_t)(n0 + n) * K + k0 + 2 * kp) = pack2h(h0, h1);
    }
}

// ---------------- kernel 1: PREP = router + fc transpose + proj transpose ----
__global__ __launch_bounds__(256)
void prep_kernel(const float* __restrict__ x,
                 const float* __restrict__ gate_w,
                 const float* __restrict__ fc_w,
                 const float* __restrict__ proj_w,
                 __half* __restrict__ fcwT,
                 __half* __restrict__ prjT,
                 float* __restrict__ out_logits) {
    __shared__ float tbuf[32 * 33];
    int bid = blockIdx.x;
    if (bid < NB_ROUTER) {
        // ---- router + x fp16 cast: 8 tokens per block (one per warp) ----
        int warp = bid * 8 + (threadIdx.x >> 5);
        int lane = threadIdx.x & 31;
        const float* xp = x + (size_t)warp * DH;
        float acc[NEXP];
#pragma unroll
        for (int e = 0; e < NEXP; e++) acc[e] = 0.0f;
#pragma unroll
        for (int i = 0; i < DH / 128; i++) {
            int d = i * 128 + lane * 4;
            float4 v = *(const float4*)(xp + d);
            uint2 hv;
            hv.x = pack2h(__float2half_rn(v.x), __float2half_rn(v.y));
            hv.y = pack2h(__float2half_rn(v.z), __float2half_rn(v.w));
            *(uint2*)(g_X + (size_t)warp * DH + d) = hv;
            const float* gw = gate_w + (size_t)d * NEXP;
#pragma unroll
            for (int e = 0; e < NEXP; e++)
                acc[e] += v.x * gw[e] + v.y * gw[NEXP + e]
                        + v.z * gw[2 * NEXP + e] + v.w * gw[3 * NEXP + e];
        }
#pragma unroll
        for (int e = 0; e < NEXP; e++)
#pragma unroll
            for (int o = 16; o > 0; o >>= 1)
                acc[e] += __shfl_xor_sync(0xffffffffu, acc[e], o);
        if (lane == 0) {
            if (out_logits)
#pragma unroll
                for (int e = 0; e < NEXP; e++) out_logits[warp * NEXP + e] = acc[e];
            int e0 = 0;
#pragma unroll
            for (int e = 1; e < NEXP; e++) if (acc[e] > acc[e0]) e0 = e;
            int e1 = (e0 == 0) ? 1 : 0;
#pragma unroll
            for (int e = 0; e < NEXP; e++) if (e != e0 && acc[e] > acc[e1]) e1 = e;
            float dlt = expf(acc[e1] - acc[e0]);
            float w0 = 1.0f / (1.0f + dlt);
            float w1 = dlt / (1.0f + dlt);
            g_eid[warp * 2 + 0] = e0; g_eid[warp * 2 + 1] = e1;
            g_wk [warp * 2 + 0] = w0; g_wk [warp * 2 + 1] = w1;
            atomicAdd(&g_count[e0], 1);
            atomicAdd(&g_count[e1], 1);
        }
    } else if (bid < NB_ROUTER + NB_FC) {
        // ---- fc_w transpose: [DH, FH] -> [FH, DH] fp16, K=DH N=FH ----
        int b = bid - NB_ROUTER;
        int e = b / (128 * 32);
        int rem = b % (128 * 32);
        int n0 = (rem % 128) * 32;
        int k0 = (rem / 128) * 32;
        transpose_tile(fc_w + (size_t)e * DH * FH, fcwT + (size_t)e * FH * DH,
                       DH, FH, n0, k0, tbuf);
    } else {
        // ---- proj_w transpose: [FH, DH] -> [DH, FH] fp16, K=FH N=DH ----
        int b = bid - NB_ROUTER - NB_FC;
        int e = b / (32 * 128);
        int rem = b % (32 * 128);
        int n0 = (rem % 32) * 32;
        int k0 = (rem / 32) * 32;
        transpose_tile(proj_w + (size_t)e * FH * DH, prjT + (size_t)e * DH * FH,
                       FH, DH, n0, k0, tbuf);
    }
}

// ---------------- kernel 2: fused scan + scatter (single block) --------------
__global__ void scan_scatter_kernel() {
    if (threadIdx.x == 0) {
        int acc = 0; g_off[0] = 0;
#pragma unroll
        for (int e = 0; e < NEXP; e++) { acc += g_count[e]; g_off[e + 1] = acc; }
    }
    __syncthreads();
    for (int t = threadIdx.x; t < NTOK; t += blockDim.x) {
#pragma unroll
        for (int k = 0; k < TOPK; k++) {
            int e = g_eid[t * 2 + k];
            int pos = g_off[e] + atomicAdd(&g_cursor[e], 1);
            g_tok[pos] = t;
            g_wt[pos]  = g_wk[t * 2 + k];
            g_slot[t * 2 + k] = pos;
        }
    }
}

// ---------------- warp-level 64x32 single-pass compute over 64-wide stage ---
struct WarpAcc { float a[4][4][4]; };   // [mi][nfrag][frag]

template <typename F>
__device__ __forceinline__ void compute_stage(uint32_t stb, int lane, int wm, int wn,
                                              WarpAcc& W, F&& issue_chunk) {
#pragma unroll
    for (int q = 0; q < 4; q++) {
        issue_chunk(q);                     // 2 cp16/thread of next stage
        int kk = q * 16;
        uint32_t ah[4][4];
        uint32_t aoff = stb + OFF_A
                      + (uint32_t)(wm + (lane & 15)) * SROW_B
                      + (uint32_t)(kk + ((lane >> 4) << 3)) * 2;
#pragma unroll
        for (int mi = 0; mi < 4; mi++)
            ldsm_x4(ah[mi], aoff + mi * 16 * SROW_B);
        int bgrp = lane >> 3;
        uint32_t boff = stb + OFF_B
                      + (uint32_t)(wn + (lane & 7) + ((bgrp & 2) << 2)) * SROW_B
                      + (uint32_t)(kk + ((bgrp & 1) << 3)) * 2;
#pragma unroll
        for (int p = 0; p < 2; p++) {           // n-frag pair (2p, 2p+1)
            uint32_t th[4];
            ldsm_x4(th, boff + p * 16 * SROW_B);
#pragma unroll
            for (int mi = 0; mi < 4; mi++) {
                mma16816(W.a[mi][2 * p],     ah[mi], th[0], th[1]);
                mma16816(W.a[mi][2 * p + 1], ah[mi], th[2], th[3]);
            }
        }
    }
}

// ---------------- GEMM1: H = gelu(x@fc_w + b), 128x128, KC=64, 2 CTA/SM -----
__global__ __launch_bounds__(BLOCK, 2)
void gemm1_mma(const float* __restrict__ fc_b) {
    int e = blockIdx.z;
    int row0 = g_off[e];
    int rows = g_off[e + 1] - row0;
    int m0 = blockIdx.x * 128;
    if (m0 >= rows) return;
    int n0 = blockIdx.y * 128;

    extern __shared__ char smem[];
    uint32_t sb = smem_u32(smem);
    int tid = threadIdx.x, wid = tid >> 5, lane = tid & 31;

    int* s_tok = (int*)(smem + NSTAGE * STAGE_B);
    if (tid < 128) s_tok[tid] = (m0 + tid < rows) ? g_tok[row0 + m0 + tid] : -1;
    __syncthreads();

    const __half* B = g_fcwT + (size_t)e * FH * DH + (size_t)n0 * DH;
    const int NC = DH / 64;   // 16 stages

    // quarter q of stage c: q<2 -> A sites, q>=2 -> B sites (2 cp16/thread)
    auto issue = [&](int c, int q) {
        uint32_t stb = sb + (c & 1) * STAGE_B;
        int kt = c * 64;
        if (q < 2) {
#pragma unroll
            for (int i = 0; i < 2; i++) {
                int u = tid + (2 * q + i) * BLOCK;   // 0..1023
                int row = u >> 3, ch = u & 7;
                uint32_t dst = stb + OFF_A + row * SROW_B + ch * 16;
                int t = s_tok[row];
                cp16(dst, g_X + (size_t)(t < 0 ? 0 : t) * DH + kt + ch * 8, t < 0 ? 0 : 16);
            }
        } else {
#pragma unroll
            for (int i = 0; i < 2; i++) {
                int u = tid + (2 * (q - 2) + i) * BLOCK;
                int row = u >> 3, ch = u & 7;
                uint32_t dst = stb + OFF_B + row * SROW_B + ch * 16;
                cp16(dst, B + (size_t)row * DH + kt + ch * 8, 16);
            }
        }
    };

    WarpAcc W;
#pragma unroll
    for (int mi = 0; mi < 4; mi++)
#pragma unroll
        for (int nf = 0; nf < 4; nf++)
#pragma unroll
            for (int r = 0; r < 4; r++) W.a[mi][nf][r] = 0.0f;

    int wm = (wid & 1) * 64, wn = (wid >> 1) * 32;

#pragma unroll
    for (int q = 0; q < 4; q++) issue(0, q);
    CP_COMMIT();
    for (int c = 0; c < NC; c++) {
        CP_WAIT0();
        __syncthreads();
        bool more = (c + 1 < NC);
        compute_stage(sb + (c & 1) * STAGE_B, lane, wm, wn, W,
                      [&](int q) { if (more) issue(c + 1, q); });
        CP_COMMIT();
    }

    const float* bias = fc_b + (size_t)e * FH;
#pragma unroll
    for (int mi = 0; mi < 4; mi++) {
#pragma unroll
        for (int rh = 0; rh < 2; rh++) {
            int m = wm + mi * 16 + (lane >> 2) + rh * 8;
            if (m0 + m >= rows) continue;
            size_t slot = (size_t)row0 + m0 + m;
#pragma unroll
            for (int nf = 0; nf < 4; nf++) {
                int n = n0 + wn + nf * 8 + 2 * (lane & 3);
                float2 bb = *(const float2*)(bias + n);
                float v0 = gelu_new(W.a[mi][nf][2 * rh + 0] + bb.x);
                float v1 = gelu_new(W.a[mi][nf][2 * rh + 1] + bb.y);
                *(uint32_t*)(g_H + slot * FH + n) =
                    pack2h(__float2half_rn(v0), __float2half_rn(v1));
            }
        }
    }
}

// ---------------- GEMM2: O = wt * (H@proj_w + b), 128x128, KC=64, 2 CTA/SM --
__global__ __launch_bounds__(BLOCK, 2)
void gemm2_mma(const float* __restrict__ proj_b) {
    int e = blockIdx.z;
    int row0 = g_off[e];
    int rows = g_off[e + 1] - row0;
    int m0 = blockIdx.x * 128;
    if (m0 >= rows) return;
    int n0 = blockIdx.y * 128;

    extern __shared__ char smem[];
    uint32_t sb = smem_u32(smem);
    int tid = threadIdx.x, wid = tid >> 5, lane = tid & 31;

    const __half* B = g_prjT + (size_t)e * DH * FH + (size_t)n0 * FH;
    const int NC = FH / 64;   // 64 stages

    auto issue = [&](int c, int q) {
        uint32_t stb = sb + (c & 1) * STAGE_B;
        int kt = c * 64;
        if (q < 2) {
#pragma unroll
            for (int i = 0; i < 2; i++) {
                int u = tid + (2 * q + i) * BLOCK;
                int row = u >> 3, ch = u & 7;
                uint32_t dst = stb + OFF_A + row * SROW_B + ch * 16;
                bool ok = (m0 + row) < rows;
                size_t slot = (size_t)row0 + m0 + (ok ? row : 0);
                cp16(dst, g_H + slot * FH + kt + ch * 8, ok ? 16 : 0);
            }
        } else {
#pragma unroll
            for (int i = 0; i < 2; i++) {
                int u = tid + (2 * (q - 2) + i) * BLOCK;
                int row = u >> 3, ch = u & 7;
                uint32_t dst = stb + OFF_B + row * SROW_B + ch * 16;
                cp16(dst, B + (size_t)row * FH + kt + ch * 8, 16);
            }
        }
    };

    WarpAcc W;
#pragma unroll
    for (int mi = 0; mi < 4; mi++)
#pragma unroll
        for (int nf = 0; nf < 4; nf++)
#pragma unroll
            for (int r = 0; r < 4; r++) W.a[mi][nf][r] = 0.0f;

    int wm = (wid & 1) * 64, wn = (wid >> 1) * 32;

#pragma unroll
    for (int q = 0; q < 4; q++) issue(0, q);
    CP_COMMIT();
    for (int c = 0; c < NC; c++) {
        CP_WAIT0();
        __syncthreads();
        bool more = (c + 1 < NC);
        compute_stage(sb + (c & 1) * STAGE_B, lane, wm, wn, W,
                      [&](int q) { if (more) issue(c + 1, q); });
        CP_COMMIT();
    }

    const float* bias = proj_b + (size_t)e * DH;
#pragma unroll
    for (int mi = 0; mi < 4; mi++) {
#pragma unroll
        for (int rh = 0; rh < 2; rh++) {
            int m = wm + mi * 16 + (lane >> 2) + rh * 8;
            if (m0 + m >= rows) continue;
            size_t slot = (size_t)row0 + m0 + m;
            float w = g_wt[slot];
#pragma unroll
            for (int nf = 0; nf < 4; nf++) {
                int n = n0 + wn + nf * 8 + 2 * (lane & 3);
                float2 bb = *(const float2*)(bias + n);
                float v0 = w * (W.a[mi][nf][2 * rh + 0] + bb.x);
                float v1 = w * (W.a[mi][nf][2 * rh + 1] + bb.y);
                *(float2*)(g_O + slot * DH + n) = make_float2(v0, v1);
            }
        }
    }
}

// ---------------- combine (+ counter reset for next call) --------------------
__global__ void combine_kernel(float* __restrict__ out) {
    if (blockIdx.x == 0 && threadIdx.x < NEXP) {
        g_count[threadIdx.x] = 0;
        g_cursor[threadIdx.x] = 0;
    }
    int idx = blockIdx.x * blockDim.x + threadIdx.x;
    const int DQ = DH / 4;
    if (idx >= NTOK * DQ) return;
    int t = idx / DQ;
    int dq = idx - t * DQ;
    int s0 = g_slot[t * 2 + 0];
    int s1 = g_slot[t * 2 + 1];
    const float4* o0 = (const float4*)(g_O + (size_t)s0 * DH) + dq;
    const float4* o1 = (const float4*)(g_O + (size_t)s1 * DH) + dq;
    float4 a = *o0, b = *o1;
    ((float4*)(out + (size_t)t * DH))[dq] =
        make_float4(a.x + b.x, a.y + b.y, a.z + b.z, a.w + b.w);
}

// ---------------- launch -----------------------------------------------------
extern "C" void kernel_launch(void* const* d_in, const int* in_sizes, int n_in,
                              void* d_out, int out_size) {
    const float* x      = (const float*)d_in[0];
    const float* gate_w = (const float*)d_in[1];
    const float* fc_w   = (const float*)d_in[2];
    const float* fc_b   = (const float*)d_in[3];
    const float* proj_w = (const float*)d_in[4];
    const float* proj_b = (const float*)d_in[5];

    float* out = (float*)d_out;
    float* out_logits =
        (out_size >= NTOK * DH + NTOK * NEXP) ? (out + (size_t)NTOK * DH) : nullptr;

    cudaFuncSetAttribute(gemm1_mma, cudaFuncAttributeMaxDynamicSharedMemorySize, SMEM_G1);
    cudaFuncSetAttribute(gemm2_mma, cudaFuncAttributeMaxDynamicSharedMemorySize, SMEM_G2);

    __half *fh, *ph;
    cudaGetSymbolAddress((void**)&fh, g_fcwT);
    cudaGetSymbolAddress((void**)&ph, g_prjT);

    // ncu profiles the 4th launch -> gemm2 this round.
    prep_kernel<<<NB_PREP, 256>>>(x, gate_w, fc_w, proj_w, fh, ph, out_logits); // 1
    scan_scatter_kernel<<<1, 1024>>>();                                          // 2
    gemm1_mma<<<dim3(NTOK / 128, FH / 128, NEXP), BLOCK, SMEM_G1>>>(fc_b);       // 3
    gemm2_mma<<<dim3(NTOK / 128, DH / 128, NEXP), BLOCK, SMEM_G2>>>(proj_b);     // 4  <- profiled
    combine_kernel<<<(NTOK * (DH / 4) + 255) / 256, 256>>>(out);                 // 5

    (void)n_in; (void)in_sizes;
}